// round 8
// baseline (speedup 1.0000x reference)
#include <cuda_runtime.h>
#include <cuda_bf16.h>
#include <cstdint>

#define T_  64
#define B_  32
#define E_  512
#define H_  8
#define F_  2048
#define TB_ (T_*B_)        // 2048
#define ROWS_ (T_*T_*B_)   // 131072

// ---------------- scratch ----------------------------------------------------
__device__ float g_qkv[TB_ * 3 * E_];
__device__ float g_w[TB_ * H_ * T_];
__device__ float g_attn[TB_ * E_];
__device__ float g_ao[TB_ * E_];
__device__ float g_h[TB_ * E_];
__device__ float g_f1[TB_ * F_];
__device__ float g_f2[TB_ * E_];
__device__ __nv_bfloat16 g_arel[(size_t)ROWS_ * E_];   // relation in bf16 (134MB)
__device__ __nv_bfloat16 g_bw[(H_/2) * E_ * 256];      // [hp][k][256]: head pair, interleaved ra/rb

// ---------------- helpers ------------------------------------------------------
__device__ __forceinline__ uint32_t smem_u32(const void* p) {
    return (uint32_t)__cvta_generic_to_shared(p);
}
__device__ __forceinline__ void ldsm_x4(uint32_t& r0, uint32_t& r1, uint32_t& r2, uint32_t& r3, uint32_t a) {
    asm volatile("ldmatrix.sync.aligned.m8n8.x4.shared.b16 {%0,%1,%2,%3},[%4];"
                 : "=r"(r0), "=r"(r1), "=r"(r2), "=r"(r3) : "r"(a));
}
__device__ __forceinline__ void ldsm_x4_t(uint32_t& r0, uint32_t& r1, uint32_t& r2, uint32_t& r3, uint32_t a) {
    asm volatile("ldmatrix.sync.aligned.m8n8.x4.trans.shared.b16 {%0,%1,%2,%3},[%4];"
                 : "=r"(r0), "=r"(r1), "=r"(r2), "=r"(r3) : "r"(a));
}
__device__ __forceinline__ void mma16816(float* c, const uint32_t* a, const uint32_t* b) {
    asm volatile("mma.sync.aligned.m16n8k16.row.col.f32.bf16.bf16.f32 "
                 "{%0,%1,%2,%3},{%4,%5,%6,%7},{%8,%9},{%0,%1,%2,%3};"
                 : "+f"(c[0]), "+f"(c[1]), "+f"(c[2]), "+f"(c[3])
                 : "r"(a[0]), "r"(a[1]), "r"(a[2]), "r"(a[3]), "r"(b[0]), "r"(b[1]));
}
__device__ __forceinline__ void mma_tf32(float* c, const float* a, const float* b) {
    asm volatile("mma.sync.aligned.m16n8k8.row.col.f32.tf32.tf32.f32 "
                 "{%0,%1,%2,%3},{%4,%5,%6,%7},{%8,%9},{%0,%1,%2,%3};"
                 : "+f"(c[0]), "+f"(c[1]), "+f"(c[2]), "+f"(c[3])
                 : "r"(__float_as_uint(a[0])), "r"(__float_as_uint(a[1])),
                   "r"(__float_as_uint(a[2])), "r"(__float_as_uint(a[3])),
                   "r"(__float_as_uint(b[0])), "r"(__float_as_uint(b[1])));
}
__device__ __forceinline__ uint32_t f2bf2(float x, float y) {
    __nv_bfloat162 t = __floats2bfloat162_rn(x, y);
    return *reinterpret_cast<uint32_t*>(&t);
}
__device__ __forceinline__ float to_tf32(float x) {
    float y;
    asm("cvt.rna.tf32.f32 %0, %1;" : "=f"(y) : "f"(x));
    return y;
}
__device__ __forceinline__ float4 to_tf32_4(float4 v) {
    return make_float4(to_tf32(v.x), to_tf32(v.y), to_tf32(v.z), to_tf32(v.w));
}
#define CP_ASYNC16(saddr, gptr) \
    asm volatile("cp.async.cg.shared.global [%0], [%1], 16;" :: "r"(saddr), "l"(gptr) : "memory")
#define CP_COMMIT() asm volatile("cp.async.commit_group;" ::: "memory")
#define CP_WAIT1()  asm volatile("cp.async.wait_group 1;" ::: "memory")
#define CP_WAIT0()  asm volatile("cp.async.wait_group 0;" ::: "memory")

// ---------------- prepass: relation fp32 -> bf16 ------------------------------
__global__ __launch_bounds__(256) void cvt_rel(const float* __restrict__ rel)
{
    size_t i = ((size_t)blockIdx.x * 256 + threadIdx.x) * 8;
    float4 a = *(const float4*)(rel + i);
    float4 b = *(const float4*)(rel + i + 4);
    uint4 v = make_uint4(f2bf2(a.x, a.y), f2bf2(a.z, a.w),
                         f2bf2(b.x, b.y), f2bf2(b.z, b.w));
    *(uint4*)((char*)g_arel + i * 2) = v;
}

// ---------------- prepass: head-pair interleaved bf16 weights [hp][k][256] ----
// For head h = 2hp + g: col g*128 + 2d = ra_d, col g*128 + 2d+1 = rb_d.
__global__ __launch_bounds__(256) void build_bw(const float* __restrict__ relw)
{
    int idx = blockIdx.x * 256 + threadIdx.x;    // 262144 = 8 heads * 512 k * 64 d
    int d = idx & 63;
    int k = (idx >> 6) & 511;
    int h = idx >> 15;
    int hp = h >> 1, g = h & 1;
    size_t base = ((size_t)hp*E_ + k) * 256 + g*128 + 2*d;
    g_bw[base    ] = __float2bfloat16(relw[(size_t)k*(2*E_) + h*64 + d]);
    g_bw[base + 1] = __float2bfloat16(relw[(size_t)k*(2*E_) + E_ + h*64 + d]);
}

// ---------------- fused relation GEMM (bf16 HMMA, 512 thr, 256x256 tile) ------
// CTA: 256 rel-rows x head pair (N=256 interleaved). 16 warps 4x4, warp tile 64x64.
// K=512, 8 stages of 64, 3 smem buffers, prefetch after barrier.
#define SA_STRIDE 32768
#define SB_STRIDE 32768
#define SB_BASE_  98304
#define RELW_SMEM 196608
__global__ void __launch_bounds__(512, 1) relw_mma(const float* __restrict__ relb)
{
    extern __shared__ char smem[];
    const uint32_t AsBase = smem_u32(smem);
    const uint32_t BsBase = AsBase + SB_BASE_;
    float* red = (float*)smem;

    const int hp  = blockIdx.x;            // heads 2hp, 2hp+1
    const int n0  = blockIdx.y * 256;
    const int tid = threadIdx.x;
    const int lane = tid & 31, warp = tid >> 5;
    const int warp_m = warp & 3, warp_n = warp >> 2;   // 4 x 4, warp tile 64x64

    float acc[4][8][4];
    #pragma unroll
    for (int i = 0; i < 4; i++)
        #pragma unroll
        for (int j = 0; j < 8; j++)
            #pragma unroll
            for (int k = 0; k < 4; k++) acc[i][j][k] = 0.f;

    const __nv_bfloat16* Ag = g_arel + (size_t)n0 * E_;
    const __nv_bfloat16* Bg = g_bw + (size_t)hp * E_ * 256;

    auto load_stage = [&](int s, int buf) {
        uint32_t Ab = AsBase + buf * SA_STRIDE;
        #pragma unroll
        for (int c = 0; c < 4; c++) {
            int idx = c * 512 + tid;          // 2048 chunks (256 rows x 128B)
            int row = idx >> 3, cg = idx & 7;
            CP_ASYNC16(Ab + row*128 + (((cg ^ (row & 7)) << 4)),
                       Ag + (size_t)row * E_ + s*64 + cg*8);
        }
        uint32_t Bb = BsBase + buf * SB_STRIDE;
        #pragma unroll
        for (int c = 0; c < 4; c++) {
            int idx = c * 512 + tid;          // 2048 chunks (64 k-rows x 512B)
            int kr = idx >> 5, ng = idx & 31;
            CP_ASYNC16(Bb + kr*512 + (((ng ^ (kr & 7)) << 4)),
                       Bg + (size_t)(s*64 + kr) * 256 + ng*8);
        }
        CP_COMMIT();
    };

    load_stage(0, 0);
    load_stage(1, 1);

    const int a_r  = warp_m*64 + (lane & 15);          // +mi*16
    const int a_kc = (lane >> 4) << 3;                 // +ks*16
    const int b_kr = lane & 15;                        // +ks*16
    const int b_nc = warp_n*64 + ((lane >> 4) << 3);   // +g*16

    #pragma unroll
    for (int s = 0; s < 8; s++) {
        if (s < 7) CP_WAIT1(); else CP_WAIT0();
        __syncthreads();
        if (s < 6) load_stage(s + 2, (s + 2) % 3);

        const uint32_t Ab = AsBase + (s % 3) * SA_STRIDE;
        const uint32_t Bb = BsBase + (s % 3) * SB_STRIDE;

        #pragma unroll
        for (int ks = 0; ks < 4; ks++) {
            uint32_t a[4][4];
            #pragma unroll
            for (int mi = 0; mi < 4; mi++) {
                int r  = a_r + mi*16;
                int kc = a_kc + ks*16;
                ldsm_x4(a[mi][0], a[mi][1], a[mi][2], a[mi][3],
                        Ab + r*128 + ((((kc >> 3) ^ (r & 7)) << 4)));
            }
            uint32_t b[8][2];
            #pragma unroll
            for (int g = 0; g < 4; g++) {
                int krow = b_kr + ks*16;
                int ncol = b_nc + g*16;
                ldsm_x4_t(b[2*g][0], b[2*g][1], b[2*g+1][0], b[2*g+1][1],
                          Bb + krow*512 + ((((ncol >> 3) ^ (krow & 7)) << 4)));
            }
            #pragma unroll
            for (int mi = 0; mi < 4; mi++)
                #pragma unroll
                for (int nf = 0; nf < 8; nf++)
                    mma16816(acc[mi][nf], a[mi], b[nf]);
        }
    }

    // ---- fused epilogue ---------------------------------------------------------
    // warp covers cols [warp_n*64, warp_n*64+64) of the 256 interleaved cols.
    // head g = warp_n>>1; within-head d = (warp_n&1)*32 + nf*4 + tig.
    const int tig = lane & 3, grp = lane >> 2;
    const int ghead = warp_n >> 1;          // 0/1 -> head 2hp+ghead
    const int hh = 2*hp + ghead;
    const int half = warp_n & 1;            // which 32-d half of the head
    float part[4][2] = {{0.f,0.f},{0.f,0.f},{0.f,0.f},{0.f,0.f}};
    #pragma unroll
    for (int nf = 0; nf < 8; nf++) {
        int d = half*32 + nf*4 + tig;
        float bra = relb[hh*64 + d];
        float brb = relb[E_ + hh*64 + d];
        #pragma unroll
        for (int mi = 0; mi < 4; mi++)
            #pragma unroll
            for (int hf = 0; hf < 2; hf++) {
                int r  = warp_m*64 + mi*16 + grp + hf*8;
                int n  = n0 + r;
                int b  = n & 31;
                int ji = n >> 5;
                int ii = ji & 63, jj = ji >> 6;
                float q = g_qkv[(size_t)(ii*B_ + b) * (3*E_) + hh*64 + d];
                float k = g_qkv[(size_t)(jj*B_ + b) * (3*E_) + E_ + hh*64 + d];
                part[mi][hf] += (acc[mi][nf][hf*2+0] + bra + q) * (acc[mi][nf][hf*2+1] + brb + k);
            }
    }
    #pragma unroll
    for (int mi = 0; mi < 4; mi++)
        #pragma unroll
        for (int hf = 0; hf < 2; hf++) {
            float v = part[mi][hf];
            v += __shfl_xor_sync(~0u, v, 1);
            v += __shfl_xor_sync(~0u, v, 2);
            part[mi][hf] = v;
        }
    __syncthreads();   // mainloop smem dead; safe to alias red
    if (tig == 0) {
        #pragma unroll
        for (int mi = 0; mi < 4; mi++)
            #pragma unroll
            for (int hf = 0; hf < 2; hf++) {
                int r = warp_m*64 + mi*16 + grp + hf*8;
                red[(r*2 + ghead)*2 + half] = part[mi][hf];
            }
    }
    __syncthreads();
    {
        int r = tid >> 1, g = tid & 1;        // 256 rows x 2 heads = 512 outputs
        int n  = n0 + r;
        int b  = n & 31;
        int ji = n >> 5;
        int ii = ji & 63, jj = ji >> 6;
        g_w[((size_t)(ii*B_ + b) * H_ + (2*hp + g)) * T_ + jj] =
            (red[(r*2 + g)*2] + red[(r*2 + g)*2 + 1]) * 0.015625f;
    }
}

// ---------------- tf32 GEMM: 128x128 tile, K-stage 32, padded-scalar smem -----
#define PA_ 36
#define PB_ 136
template<bool BTRANS, int EPI>
__global__ __launch_bounds__(256) void gemm_tf32(
    const float* __restrict__ A, const float* __restrict__ Bm,
    const float* __restrict__ bias, const float* __restrict__ add,
    float* __restrict__ C, int M, int N, int K)
{
    extern __shared__ float sm[];
    const int AW = 128 * PA_;
    const int BW = BTRANS ? 128 * PA_ : 32 * PB_;
    float* Asm[2] = { sm, sm + AW };
    float* Bsm[2] = { sm + 2*AW, sm + 2*AW + BW };

    const int tid = threadIdx.x;
    const int lane = tid & 31, warp = tid >> 5;
    const int wm = warp >> 1, wn = warp & 1;
    const int grp = lane >> 2, tig = lane & 3;
    const int m0 = blockIdx.y * 128;
    const int n0 = blockIdx.x * 128;

    float acc[2][8][4];
    #pragma unroll
    for (int i = 0; i < 2; i++)
        #pragma unroll
        for (int j = 0; j < 8; j++)
            #pragma unroll
            for (int k = 0; k < 4; k++) acc[i][j][k] = 0.f;

    const int S = K >> 5;
    float4 pa[4], pb[4];

    #pragma unroll
    for (int it = 0; it < 4; it++) {
        int idx = it * 1024 + tid * 4;
        pa[it] = *(const float4*)(A + (size_t)(m0 + (idx >> 5)) * K + (idx & 31));
        if (BTRANS) pb[it] = *(const float4*)(Bm + (size_t)(n0 + (idx >> 5)) * K + (idx & 31));
        else        pb[it] = *(const float4*)(Bm + (size_t)(idx >> 7) * N + n0 + (idx & 127));
    }
    #pragma unroll
    for (int it = 0; it < 4; it++) {
        int idx = it * 1024 + tid * 4;
        *(float4*)&Asm[0][(idx >> 5) * PA_ + (idx & 31)] = to_tf32_4(pa[it]);
        if (BTRANS) *(float4*)&Bsm[0][(idx >> 5) * PA_ + (idx & 31)] = to_tf32_4(pb[it]);
        else        *(float4*)&Bsm[0][(idx >> 7) * PB_ + (idx & 127)] = to_tf32_4(pb[it]);
    }
    __syncthreads();

    for (int s = 0; s < S; s++) {
        if (s < S - 1) {
            int k0 = (s + 1) * 32;
            #pragma unroll
            for (int it = 0; it < 4; it++) {
                int idx = it * 1024 + tid * 4;
                pa[it] = *(const float4*)(A + (size_t)(m0 + (idx >> 5)) * K + k0 + (idx & 31));
                if (BTRANS) pb[it] = *(const float4*)(Bm + (size_t)(n0 + (idx >> 5)) * K + k0 + (idx & 31));
                else        pb[it] = *(const float4*)(Bm + (size_t)(k0 + (idx >> 7)) * N + n0 + (idx & 127));
            }
        }
        const float* Ab = Asm[s & 1];
        const float* Bb = Bsm[s & 1];
        #pragma unroll
        for (int ks = 0; ks < 4; ks++) {
            float a[2][4];
            #pragma unroll
            for (int mi = 0; mi < 2; mi++) {
                int r = wm*32 + mi*16 + grp;
                int c = ks*8 + tig;
                a[mi][0] = Ab[r * PA_ + c];
                a[mi][1] = Ab[(r + 8) * PA_ + c];
                a[mi][2] = Ab[r * PA_ + c + 4];
                a[mi][3] = Ab[(r + 8) * PA_ + c + 4];
            }
            float b[8][2];
            #pragma unroll
            for (int nf = 0; nf < 8; nf++) {
                int n = wn*64 + nf*8 + grp;
                if (BTRANS) {
                    b[nf][0] = Bb[n * PA_ + ks*8 + tig];
                    b[nf][1] = Bb[n * PA_ + ks*8 + tig + 4];
                } else {
                    b[nf][0] = Bb[(ks*8 + tig) * PB_ + n];
                    b[nf][1] = Bb[(ks*8 + tig + 4) * PB_ + n];
                }
            }
            #pragma unroll
            for (int mi = 0; mi < 2; mi++)
                #pragma unroll
                for (int nf = 0; nf < 8; nf++)
                    mma_tf32(acc[mi][nf], a[mi], b[nf]);
        }
        if (s < S - 1) {
            __syncthreads();
            float* Ac = Asm[(s + 1) & 1];
            float* Bc = Bsm[(s + 1) & 1];
            #pragma unroll
            for (int it = 0; it < 4; it++) {
                int idx = it * 1024 + tid * 4;
                *(float4*)&Ac[(idx >> 5) * PA_ + (idx & 31)] = to_tf32_4(pa[it]);
                if (BTRANS) *(float4*)&Bc[(idx >> 5) * PA_ + (idx & 31)] = to_tf32_4(pb[it]);
                else        *(float4*)&Bc[(idx >> 7) * PB_ + (idx & 127)] = to_tf32_4(pb[it]);
            }
            __syncthreads();
        }
    }

    #pragma unroll
    for (int mi = 0; mi < 2; mi++)
        #pragma unroll
        for (int hf = 0; hf < 2; hf++) {
            int row = m0 + wm*32 + mi*16 + grp + hf*8;
            #pragma unroll
            for (int nf = 0; nf < 8; nf++) {
                int col = n0 + wn*64 + nf*8 + tig*2;
                float v0 = acc[mi][nf][hf*2 + 0] + bias[col];
                float v1 = acc[mi][nf][hf*2 + 1] + bias[col + 1];
                if (EPI == 1) { v0 = fmaxf(v0, 0.f); v1 = fmaxf(v1, 0.f); }
                if (EPI == 2) {
                    v0 += add[(size_t)row * N + col];
                    v1 += add[(size_t)row * N + col + 1];
                }
                *(float2*)(C + (size_t)row * N + col) = make_float2(v0, v1);
            }
        }
}

// ---------------- softmax over j + attn = p @ v ------------------------------
__global__ __launch_bounds__(256) void softmax_attn_kernel()
{
    int ib = blockIdx.x;
    int b  = ib & 31;
    __shared__ float p[H_][T_];
    int t = threadIdx.x;
    int w = t >> 5, l = t & 31;

    float v0 = g_w[((size_t)ib*H_ + w)*T_ + l];
    float v1 = g_w[((size_t)ib*H_ + w)*T_ + l + 32];
    float mx = fmaxf(v0, v1);
    #pragma unroll
    for (int o = 16; o; o >>= 1) mx = fmaxf(mx, __shfl_xor_sync(~0u, mx, o));
    float e0 = expf(v0 - mx), e1 = expf(v1 - mx);
    float s = e0 + e1;
    #pragma unroll
    for (int o = 16; o; o >>= 1) s += __shfl_xor_sync(~0u, s, o);
    float inv = 1.0f / s;
    p[w][l]      = e0 * inv;
    p[w][l + 32] = e1 * inv;
    __syncthreads();

    #pragma unroll
    for (int c0 = 0; c0 < E_; c0 += 256) {
        int c = c0 + t;
        int hh = c >> 6, d = c & 63;
        float acc = 0.f;
        #pragma unroll 8
        for (int j = 0; j < T_; j++)
            acc += p[hh][j] * g_qkv[(size_t)(j*B_ + b) * (3*E_) + 2*E_ + hh*64 + d];
        g_attn[(size_t)ib * E_ + c] = acc;
    }
}

// ---------------- layernorm ----------------------------------------------------
__global__ __launch_bounds__(256) void ln_kernel(
    const float* __restrict__ in, const float* __restrict__ g,
    const float* __restrict__ b, float* __restrict__ out)
{
    int row = blockIdx.x;
    const float* r = in + (size_t)row * E_;
    int t = threadIdx.x;
    float v0 = r[t], v1 = r[t + 256];
    float s = v0 + v1, sq = v0*v0 + v1*v1;
    #pragma unroll
    for (int o = 16; o; o >>= 1) {
        s  += __shfl_xor_sync(~0u, s,  o);
        sq += __shfl_xor_sync(~0u, sq, o);
    }
    __shared__ float ss[8], ssq[8];
    int w = t >> 5, l = t & 31;
    if (l == 0) { ss[w] = s; ssq[w] = sq; }
    __syncthreads();
    if (w == 0) {
        s  = (l < 8) ? ss[l]  : 0.f;
        sq = (l < 8) ? ssq[l] : 0.f;
        #pragma unroll
        for (int o = 4; o; o >>= 1) {
            s  += __shfl_xor_sync(~0u, s,  o);
            sq += __shfl_xor_sync(~0u, sq, o);
        }
        if (l == 0) { ss[0] = s; ssq[0] = sq; }
    }
    __syncthreads();
    float mu   = ss[0]  * (1.f / E_);
    float var  = ssq[0] * (1.f / E_) - mu * mu;
    float rstd = rsqrtf(var + 1e-5f);
    out[(size_t)row*E_ + t]       = (v0 - mu) * rstd * g[t]       + b[t];
    out[(size_t)row*E_ + t + 256] = (v1 - mu) * rstd * g[t + 256] + b[t + 256];
}

// ---------------- launch --------------------------------------------------------
extern "C" void kernel_launch(void* const* d_in, const int* in_sizes, int n_in,
                              void* d_out, int out_size)
{
    const float* x        = (const float*)d_in[0];
    const float* relation = (const float*)d_in[1];
    const float* in_w     = (const float*)d_in[2];
    const float* in_b     = (const float*)d_in[3];
    const float* rel_w    = (const float*)d_in[4];
    const float* rel_b    = (const float*)d_in[5];
    const float* out_w    = (const float*)d_in[6];
    const float* out_b    = (const float*)d_in[7];
    const float* fc1_w    = (const float*)d_in[8];
    const float* fc1_b    = (const float*)d_in[9];
    const float* fc2_w    = (const float*)d_in[10];
    const float* fc2_b    = (const float*)d_in[11];
    const float* ln1_g    = (const float*)d_in[12];
    const float* ln1_b    = (const float*)d_in[13];
    const float* ln2_g    = (const float*)d_in[14];
    const float* ln2_b    = (const float*)d_in[15];
    float* out = (float*)d_out;

    const int SM_BT = (2*128*PA_ + 2*128*PA_) * 4;
    const int SM_BN = (2*128*PA_ + 2*32*PB_) * 4;

    static float *p_qkv = nullptr, *p_attn, *p_ao, *p_h, *p_f1, *p_f2;
    if (!p_qkv) {
        cudaGetSymbolAddress((void**)&p_qkv,  g_qkv);
        cudaGetSymbolAddress((void**)&p_attn, g_attn);
        cudaGetSymbolAddress((void**)&p_ao,   g_ao);
        cudaGetSymbolAddress((void**)&p_h,    g_h);
        cudaGetSymbolAddress((void**)&p_f1,   g_f1);
        cudaGetSymbolAddress((void**)&p_f2,   g_f2);
        cudaFuncSetAttribute(relw_mma, cudaFuncAttributeMaxDynamicSharedMemorySize, RELW_SMEM);
        cudaFuncSetAttribute(gemm_tf32<true, 0>, cudaFuncAttributeMaxDynamicSharedMemorySize, SM_BT);
        cudaFuncSetAttribute(gemm_tf32<false, 1>, cudaFuncAttributeMaxDynamicSharedMemorySize, SM_BN);
        cudaFuncSetAttribute(gemm_tf32<false, 2>, cudaFuncAttributeMaxDynamicSharedMemorySize, SM_BN);
    }

    dim3 blk(256);

    // 0a. prepass: relation -> bf16 (134MB)
    cvt_rel<<<ROWS_ * E_ / (8 * 256), 256>>>(relation);
    // 0b. prepass: head-pair interleaved bf16 weights [hp][k][256]
    build_bw<<<1024, 256>>>(rel_w);

    // 1. qkv = x @ in_w^T + in_b    (tf32)
    gemm_tf32<true, 0><<<dim3(1536/128, TB_/128), blk, SM_BT>>>(x, in_w, in_b, nullptr, p_qkv, TB_, 3*E_, E_);

    // 2. relation GEMM (bf16 HMMA, 512thr 256x256 tile, 3-stage cp.async)
    relw_mma<<<dim3(H_/2, ROWS_/256), dim3(512), RELW_SMEM>>>(rel_b);

    // 3. softmax + attn
    softmax_attn_kernel<<<TB_, 256>>>();

    // 4. out proj + residual       (tf32)
    gemm_tf32<false, 2><<<dim3(E_/128, TB_/128), blk, SM_BN>>>(p_attn, out_w, out_b, x, p_ao, TB_, E_, E_);

    // 5. LN1
    ln_kernel<<<TB_, 256>>>(p_ao, ln1_g, ln1_b, p_h);

    // 6. fc1 + relu                (tf32)
    gemm_tf32<false, 1><<<dim3(F_/128, TB_/128), blk, SM_BN>>>(p_h, fc1_w, fc1_b, nullptr, p_f1, TB_, F_, E_);

    // 7. fc2 + residual h          (tf32)
    gemm_tf32<false, 2><<<dim3(E_/128, TB_/128), blk, SM_BN>>>(p_f1, fc2_w, fc2_b, p_h, p_f2, TB_, E_, F_);

    // 8. LN2 -> out
    ln_kernel<<<TB_, 256>>>(p_f2, ln2_g, ln2_b, out);
}

// round 9
// speedup vs baseline: 3.4961x; 3.4961x over previous
#include <cuda_runtime.h>
#include <cuda_bf16.h>
#include <cstdint>

#define T_  64
#define B_  32
#define E_  512
#define H_  8
#define F_  2048
#define TB_ (T_*B_)        // 2048
#define ROWS_ (T_*T_*B_)   // 131072

// ---------------- scratch ----------------------------------------------------
__device__ float g_qkv[TB_ * 3 * E_];
__device__ float g_w[TB_ * H_ * T_];
__device__ float g_attn[TB_ * E_];
__device__ float g_ao[TB_ * E_];
__device__ float g_h[TB_ * E_];
__device__ float g_f1[TB_ * F_];
__device__ float g_f2[TB_ * E_];
__device__ __nv_bfloat16 g_arel[(size_t)ROWS_ * E_];   // relation in bf16 (134MB)
__device__ __nv_bfloat16 g_bw[H_ * E_ * 128];          // [h][k][2d interleaved ra/rb]

// ---------------- helpers ------------------------------------------------------
__device__ __forceinline__ uint32_t smem_u32(const void* p) {
    return (uint32_t)__cvta_generic_to_shared(p);
}
__device__ __forceinline__ void ldsm_x4(uint32_t& r0, uint32_t& r1, uint32_t& r2, uint32_t& r3, uint32_t a) {
    asm volatile("ldmatrix.sync.aligned.m8n8.x4.shared.b16 {%0,%1,%2,%3},[%4];"
                 : "=r"(r0), "=r"(r1), "=r"(r2), "=r"(r3) : "r"(a));
}
__device__ __forceinline__ void ldsm_x4_t(uint32_t& r0, uint32_t& r1, uint32_t& r2, uint32_t& r3, uint32_t a) {
    asm volatile("ldmatrix.sync.aligned.m8n8.x4.trans.shared.b16 {%0,%1,%2,%3},[%4];"
                 : "=r"(r0), "=r"(r1), "=r"(r2), "=r"(r3) : "r"(a));
}
__device__ __forceinline__ void mma16816(float* c, const uint32_t* a, const uint32_t* b) {
    asm volatile("mma.sync.aligned.m16n8k16.row.col.f32.bf16.bf16.f32 "
                 "{%0,%1,%2,%3},{%4,%5,%6,%7},{%8,%9},{%0,%1,%2,%3};"
                 : "+f"(c[0]), "+f"(c[1]), "+f"(c[2]), "+f"(c[3])
                 : "r"(a[0]), "r"(a[1]), "r"(a[2]), "r"(a[3]), "r"(b[0]), "r"(b[1]));
}
__device__ __forceinline__ void mma_tf32(float* c, const float* a, const float* b) {
    asm volatile("mma.sync.aligned.m16n8k8.row.col.f32.tf32.tf32.f32 "
                 "{%0,%1,%2,%3},{%4,%5,%6,%7},{%8,%9},{%0,%1,%2,%3};"
                 : "+f"(c[0]), "+f"(c[1]), "+f"(c[2]), "+f"(c[3])
                 : "r"(__float_as_uint(a[0])), "r"(__float_as_uint(a[1])),
                   "r"(__float_as_uint(a[2])), "r"(__float_as_uint(a[3])),
                   "r"(__float_as_uint(b[0])), "r"(__float_as_uint(b[1])));
}
__device__ __forceinline__ uint32_t f2bf2(float x, float y) {
    __nv_bfloat162 t = __floats2bfloat162_rn(x, y);
    return *reinterpret_cast<uint32_t*>(&t);
}
__device__ __forceinline__ float to_tf32(float x) {
    float y;
    asm("cvt.rna.tf32.f32 %0, %1;" : "=f"(y) : "f"(x));
    return y;
}
__device__ __forceinline__ float4 to_tf32_4(float4 v) {
    return make_float4(to_tf32(v.x), to_tf32(v.y), to_tf32(v.z), to_tf32(v.w));
}
#define CP_ASYNC16(saddr, gptr) \
    asm volatile("cp.async.cg.shared.global [%0], [%1], 16;" :: "r"(saddr), "l"(gptr) : "memory")
#define CP_COMMIT() asm volatile("cp.async.commit_group;" ::: "memory")
#define CP_WAIT1()  asm volatile("cp.async.wait_group 1;" ::: "memory")
#define CP_WAIT0()  asm volatile("cp.async.wait_group 0;" ::: "memory")

// ---------------- prepass: relation fp32 -> bf16 ------------------------------
__global__ __launch_bounds__(256) void cvt_rel(const float* __restrict__ rel)
{
    size_t i = ((size_t)blockIdx.x * 256 + threadIdx.x) * 8;
    float4 a = *(const float4*)(rel + i);
    float4 b = *(const float4*)(rel + i + 4);
    uint4 v = make_uint4(f2bf2(a.x, a.y), f2bf2(a.z, a.w),
                         f2bf2(b.x, b.y), f2bf2(b.z, b.w));
    *(uint4*)((char*)g_arel + i * 2) = v;
}

// ---------------- prepass: interleaved bf16 weight tiles [h][k][128] ----------
__global__ __launch_bounds__(256) void build_bw(const float* __restrict__ relw)
{
    int idx = blockIdx.x * 256 + threadIdx.x;    // 262144
    int d = idx & 63;
    int k = (idx >> 6) & 511;
    int h = idx >> 15;
    g_bw[((size_t)h*E_ + k) * 128 + 2*d    ] = __float2bfloat16(relw[(size_t)k*(2*E_) + h*64 + d]);
    g_bw[((size_t)h*E_ + k) * 128 + 2*d + 1] = __float2bfloat16(relw[(size_t)k*(2*E_) + E_ + h*64 + d]);
}

// ---------------- fused relation GEMM (bf16 HMMA, 3-stage, 2 CTAs/SM) ---------
// 128x128 tile (one head), 8 warps 4(m)x2(n), warp tile 32x64, acc=64 regs.
// K=512, 8 stages of 64, 3 smem bufs (96KB), prefetch after barrier (race-free).
#define RSA_STRIDE 16384
#define RSB_BASE   49152
#define RSB_STRIDE 16384
#define RELW_SMEM  98304
__global__ void __launch_bounds__(256, 2) relw_mma(const float* __restrict__ relb)
{
    extern __shared__ char smem[];
    const uint32_t AsBase = smem_u32(smem);
    const uint32_t BsBase = AsBase + RSB_BASE;
    float* red = (float*)smem;

    const int h   = blockIdx.x;
    const int n0  = blockIdx.y * 128;
    const int tid = threadIdx.x;
    const int lane = tid & 31, warp = tid >> 5;
    const int warp_m = warp >> 1, warp_n = warp & 1;   // 4 x 2, warp tile 32x64

    float acc[2][8][4];
    #pragma unroll
    for (int i = 0; i < 2; i++)
        #pragma unroll
        for (int j = 0; j < 8; j++)
            #pragma unroll
            for (int k = 0; k < 4; k++) acc[i][j][k] = 0.f;

    const __nv_bfloat16* Ag = g_arel + (size_t)n0 * E_;
    const __nv_bfloat16* Bg = g_bw + (size_t)h * E_ * 128;

    auto load_stage = [&](int s, int buf) {
        uint32_t Ab = AsBase + buf * RSA_STRIDE;
        #pragma unroll
        for (int c = 0; c < 4; c++) {
            int idx = c * 256 + tid;          // 1024 chunks (128 rows x 128B)
            int row = idx >> 3, cg = idx & 7;
            CP_ASYNC16(Ab + row*128 + (((cg ^ (row & 7)) << 4)),
                       Ag + (size_t)row * E_ + s*64 + cg*8);
        }
        uint32_t Bb = BsBase + buf * RSB_STRIDE;
        #pragma unroll
        for (int c = 0; c < 4; c++) {
            int idx = c * 256 + tid;          // 1024 chunks (64 k-rows x 256B)
            int kr = idx >> 4, ng = idx & 15;
            CP_ASYNC16(Bb + kr*256 + (((ng ^ (kr & 7)) << 4)),
                       Bg + (size_t)(s*64 + kr) * 128 + ng*8);
        }
        CP_COMMIT();
    };

    load_stage(0, 0);
    load_stage(1, 1);

    const int a_r  = warp_m*32 + (lane & 15);          // +mi*16
    const int a_kc = (lane >> 4) << 3;                 // +ks*16
    const int b_kr = lane & 15;                        // +ks*16
    const int b_nc = warp_n*64 + ((lane >> 4) << 3);   // +g*16

    #pragma unroll
    for (int s = 0; s < 8; s++) {
        if (s < 7) CP_WAIT1(); else CP_WAIT0();
        __syncthreads();
        if (s < 6) load_stage(s + 2, (s + 2) % 3);     // safe: buf (s+2)%3 == (s-1)%3 fully consumed

        const uint32_t Ab = AsBase + (s % 3) * RSA_STRIDE;
        const uint32_t Bb = BsBase + (s % 3) * RSB_STRIDE;

        #pragma unroll
        for (int ks = 0; ks < 4; ks++) {
            uint32_t a[2][4];
            #pragma unroll
            for (int mi = 0; mi < 2; mi++) {
                int r  = a_r + mi*16;
                int kc = a_kc + ks*16;
                ldsm_x4(a[mi][0], a[mi][1], a[mi][2], a[mi][3],
                        Ab + r*128 + ((((kc >> 3) ^ (r & 7)) << 4)));
            }
            uint32_t b[8][2];
            #pragma unroll
            for (int g = 0; g < 4; g++) {
                int krow = b_kr + ks*16;
                int ncol = b_nc + g*16;
                ldsm_x4_t(b[2*g][0], b[2*g][1], b[2*g+1][0], b[2*g+1][1],
                          Bb + krow*256 + ((((ncol >> 3) ^ (krow & 7)) << 4)));
            }
            #pragma unroll
            for (int mi = 0; mi < 2; mi++)
                #pragma unroll
                for (int nf = 0; nf < 8; nf++)
                    mma16816(acc[mi][nf], a[mi], b[nf]);
        }
    }

    // ---- fused epilogue: (c0 + bra + q) * (c1 + brb + k), reduce over d --------
    const int tig = lane & 3, grp = lane >> 2;
    float part[2][2] = {{0.f, 0.f}, {0.f, 0.f}};
    #pragma unroll
    for (int nf = 0; nf < 8; nf++) {
        int d = warp_n*32 + nf*4 + tig;
        float bra = relb[h*64 + d];
        float brb = relb[E_ + h*64 + d];
        #pragma unroll
        for (int mi = 0; mi < 2; mi++)
            #pragma unroll
            for (int hf = 0; hf < 2; hf++) {
                int r  = warp_m*32 + mi*16 + grp + hf*8;
                int n  = n0 + r;
                int b  = n & 31;
                int ji = n >> 5;
                int ii = ji & 63, jj = ji >> 6;
                float q = g_qkv[(size_t)(ii*B_ + b) * (3*E_) + h*64 + d];
                float k = g_qkv[(size_t)(jj*B_ + b) * (3*E_) + E_ + h*64 + d];
                part[mi][hf] += (acc[mi][nf][hf*2+0] + bra + q) * (acc[mi][nf][hf*2+1] + brb + k);
            }
    }
    #pragma unroll
    for (int mi = 0; mi < 2; mi++)
        #pragma unroll
        for (int hf = 0; hf < 2; hf++) {
            float v = part[mi][hf];
            v += __shfl_xor_sync(~0u, v, 1);
            v += __shfl_xor_sync(~0u, v, 2);
            part[mi][hf] = v;
        }
    __syncthreads();   // mainloop smem dead; safe to alias red
    if (tig == 0) {
        #pragma unroll
        for (int mi = 0; mi < 2; mi++)
            #pragma unroll
            for (int hf = 0; hf < 2; hf++) {
                int r = warp_m*32 + mi*16 + grp + hf*8;
                red[r*2 + warp_n] = part[mi][hf];
            }
    }
    __syncthreads();
    if (tid < 128) {
        int n  = n0 + tid;
        int b  = n & 31;
        int ji = n >> 5;
        int ii = ji & 63, jj = ji >> 6;
        g_w[((size_t)(ii*B_ + b) * H_ + h) * T_ + jj] =
            (red[tid*2] + red[tid*2 + 1]) * 0.015625f;
    }
}

// ---------------- tf32 GEMM: 128x128 tile, K-stage 32, padded-scalar smem -----
#define PA_ 36
#define PB_ 136
template<bool BTRANS, int EPI>
__global__ __launch_bounds__(256) void gemm_tf32(
    const float* __restrict__ A, const float* __restrict__ Bm,
    const float* __restrict__ bias, const float* __restrict__ add,
    float* __restrict__ C, int M, int N, int K)
{
    extern __shared__ float sm[];
    const int AW = 128 * PA_;
    const int BW = BTRANS ? 128 * PA_ : 32 * PB_;
    float* Asm[2] = { sm, sm + AW };
    float* Bsm[2] = { sm + 2*AW, sm + 2*AW + BW };

    const int tid = threadIdx.x;
    const int lane = tid & 31, warp = tid >> 5;
    const int wm = warp >> 1, wn = warp & 1;
    const int grp = lane >> 2, tig = lane & 3;
    const int m0 = blockIdx.y * 128;
    const int n0 = blockIdx.x * 128;

    float acc[2][8][4];
    #pragma unroll
    for (int i = 0; i < 2; i++)
        #pragma unroll
        for (int j = 0; j < 8; j++)
            #pragma unroll
            for (int k = 0; k < 4; k++) acc[i][j][k] = 0.f;

    const int S = K >> 5;
    float4 pa[4], pb[4];

    #pragma unroll
    for (int it = 0; it < 4; it++) {
        int idx = it * 1024 + tid * 4;
        pa[it] = *(const float4*)(A + (size_t)(m0 + (idx >> 5)) * K + (idx & 31));
        if (BTRANS) pb[it] = *(const float4*)(Bm + (size_t)(n0 + (idx >> 5)) * K + (idx & 31));
        else        pb[it] = *(const float4*)(Bm + (size_t)(idx >> 7) * N + n0 + (idx & 127));
    }
    #pragma unroll
    for (int it = 0; it < 4; it++) {
        int idx = it * 1024 + tid * 4;
        *(float4*)&Asm[0][(idx >> 5) * PA_ + (idx & 31)] = to_tf32_4(pa[it]);
        if (BTRANS) *(float4*)&Bsm[0][(idx >> 5) * PA_ + (idx & 31)] = to_tf32_4(pb[it]);
        else        *(float4*)&Bsm[0][(idx >> 7) * PB_ + (idx & 127)] = to_tf32_4(pb[it]);
    }
    __syncthreads();

    for (int s = 0; s < S; s++) {
        if (s < S - 1) {
            int k0 = (s + 1) * 32;
            #pragma unroll
            for (int it = 0; it < 4; it++) {
                int idx = it * 1024 + tid * 4;
                pa[it] = *(const float4*)(A + (size_t)(m0 + (idx >> 5)) * K + k0 + (idx & 31));
                if (BTRANS) pb[it] = *(const float4*)(Bm + (size_t)(n0 + (idx >> 5)) * K + k0 + (idx & 31));
                else        pb[it] = *(const float4*)(Bm + (size_t)(k0 + (idx >> 7)) * N + n0 + (idx & 127));
            }
        }
        const float* Ab = Asm[s & 1];
        const float* Bb = Bsm[s & 1];
        #pragma unroll
        for (int ks = 0; ks < 4; ks++) {
            float a[2][4];
            #pragma unroll
            for (int mi = 0; mi < 2; mi++) {
                int r = wm*32 + mi*16 + grp;
                int c = ks*8 + tig;
                a[mi][0] = Ab[r * PA_ + c];
                a[mi][1] = Ab[(r + 8) * PA_ + c];
                a[mi][2] = Ab[r * PA_ + c + 4];
                a[mi][3] = Ab[(r + 8) * PA_ + c + 4];
            }
            float b[8][2];
            #pragma unroll
            for (int nf = 0; nf < 8; nf++) {
                int n = wn*64 + nf*8 + grp;
                if (BTRANS) {
                    b[nf][0] = Bb[n * PA_ + ks*8 + tig];
                    b[nf][1] = Bb[n * PA_ + ks*8 + tig + 4];
                } else {
                    b[nf][0] = Bb[(ks*8 + tig) * PB_ + n];
                    b[nf][1] = Bb[(ks*8 + tig + 4) * PB_ + n];
                }
            }
            #pragma unroll
            for (int mi = 0; mi < 2; mi++)
                #pragma unroll
                for (int nf = 0; nf < 8; nf++)
                    mma_tf32(acc[mi][nf], a[mi], b[nf]);
        }
        if (s < S - 1) {
            __syncthreads();
            float* Ac = Asm[(s + 1) & 1];
            float* Bc = Bsm[(s + 1) & 1];
            #pragma unroll
            for (int it = 0; it < 4; it++) {
                int idx = it * 1024 + tid * 4;
                *(float4*)&Ac[(idx >> 5) * PA_ + (idx & 31)] = to_tf32_4(pa[it]);
                if (BTRANS) *(float4*)&Bc[(idx >> 5) * PA_ + (idx & 31)] = to_tf32_4(pb[it]);
                else        *(float4*)&Bc[(idx >> 7) * PB_ + (idx & 127)] = to_tf32_4(pb[it]);
            }
            __syncthreads();
        }
    }

    #pragma unroll
    for (int mi = 0; mi < 2; mi++)
        #pragma unroll
        for (int hf = 0; hf < 2; hf++) {
            int row = m0 + wm*32 + mi*16 + grp + hf*8;
            #pragma unroll
            for (int nf = 0; nf < 8; nf++) {
                int col = n0 + wn*64 + nf*8 + tig*2;
                float v0 = acc[mi][nf][hf*2 + 0] + bias[col];
                float v1 = acc[mi][nf][hf*2 + 1] + bias[col + 1];
                if (EPI == 1) { v0 = fmaxf(v0, 0.f); v1 = fmaxf(v1, 0.f); }
                if (EPI == 2) {
                    v0 += add[(size_t)row * N + col];
                    v1 += add[(size_t)row * N + col + 1];
                }
                *(float2*)(C + (size_t)row * N + col) = make_float2(v0, v1);
            }
        }
}

// ---------------- softmax over j + attn = p @ v ------------------------------
__global__ __launch_bounds__(256) void softmax_attn_kernel()
{
    int ib = blockIdx.x;
    int b  = ib & 31;
    __shared__ float p[H_][T_];
    int t = threadIdx.x;
    int w = t >> 5, l = t & 31;

    float v0 = g_w[((size_t)ib*H_ + w)*T_ + l];
    float v1 = g_w[((size_t)ib*H_ + w)*T_ + l + 32];
    float mx = fmaxf(v0, v1);
    #pragma unroll
    for (int o = 16; o; o >>= 1) mx = fmaxf(mx, __shfl_xor_sync(~0u, mx, o));
    float e0 = expf(v0 - mx), e1 = expf(v1 - mx);
    float s = e0 + e1;
    #pragma unroll
    for (int o = 16; o; o >>= 1) s += __shfl_xor_sync(~0u, s, o);
    float inv = 1.0f / s;
    p[w][l]      = e0 * inv;
    p[w][l + 32] = e1 * inv;
    __syncthreads();

    #pragma unroll
    for (int c0 = 0; c0 < E_; c0 += 256) {
        int c = c0 + t;
        int hh = c >> 6, d = c & 63;
        float acc = 0.f;
        #pragma unroll 8
        for (int j = 0; j < T_; j++)
            acc += p[hh][j] * g_qkv[(size_t)(j*B_ + b) * (3*E_) + 2*E_ + hh*64 + d];
        g_attn[(size_t)ib * E_ + c] = acc;
    }
}

// ---------------- layernorm ----------------------------------------------------
__global__ __launch_bounds__(256) void ln_kernel(
    const float* __restrict__ in, const float* __restrict__ g,
    const float* __restrict__ b, float* __restrict__ out)
{
    int row = blockIdx.x;
    const float* r = in + (size_t)row * E_;
    int t = threadIdx.x;
    float v0 = r[t], v1 = r[t + 256];
    float s = v0 + v1, sq = v0*v0 + v1*v1;
    #pragma unroll
    for (int o = 16; o; o >>= 1) {
        s  += __shfl_xor_sync(~0u, s,  o);
        sq += __shfl_xor_sync(~0u, sq, o);
    }
    __shared__ float ss[8], ssq[8];
    int w = t >> 5, l = t & 31;
    if (l == 0) { ss[w] = s; ssq[w] = sq; }
    __syncthreads();
    if (w == 0) {
        s  = (l < 8) ? ss[l]  : 0.f;
        sq = (l < 8) ? ssq[l] : 0.f;
        #pragma unroll
        for (int o = 4; o; o >>= 1) {
            s  += __shfl_xor_sync(~0u, s,  o);
            sq += __shfl_xor_sync(~0u, sq, o);
        }
        if (l == 0) { ss[0] = s; ssq[0] = sq; }
    }
    __syncthreads();
    float mu   = ss[0]  * (1.f / E_);
    float var  = ssq[0] * (1.f / E_) - mu * mu;
    float rstd = rsqrtf(var + 1e-5f);
    out[(size_t)row*E_ + t]       = (v0 - mu) * rstd * g[t]       + b[t];
    out[(size_t)row*E_ + t + 256] = (v1 - mu) * rstd * g[t + 256] + b[t + 256];
}

// ---------------- launch --------------------------------------------------------
extern "C" void kernel_launch(void* const* d_in, const int* in_sizes, int n_in,
                              void* d_out, int out_size)
{
    const float* x        = (const float*)d_in[0];
    const float* relation = (const float*)d_in[1];
    const float* in_w     = (const float*)d_in[2];
    const float* in_b     = (const float*)d_in[3];
    const float* rel_w    = (const float*)d_in[4];
    const float* rel_b    = (const float*)d_in[5];
    const float* out_w    = (const float*)d_in[6];
    const float* out_b    = (const float*)d_in[7];
    const float* fc1_w    = (const float*)d_in[8];
    const float* fc1_b    = (const float*)d_in[9];
    const float* fc2_w    = (const float*)d_in[10];
    const float* fc2_b    = (const float*)d_in[11];
    const float* ln1_g    = (const float*)d_in[12];
    const float* ln1_b    = (const float*)d_in[13];
    const float* ln2_g    = (const float*)d_in[14];
    const float* ln2_b    = (const float*)d_in[15];
    float* out = (float*)d_out;

    const int SM_BT = (2*128*PA_ + 2*128*PA_) * 4;
    const int SM_BN = (2*128*PA_ + 2*32*PB_) * 4;

    static float *p_qkv = nullptr, *p_attn, *p_ao, *p_h, *p_f1, *p_f2;
    if (!p_qkv) {
        cudaGetSymbolAddress((void**)&p_qkv,  g_qkv);
        cudaGetSymbolAddress((void**)&p_attn, g_attn);
        cudaGetSymbolAddress((void**)&p_ao,   g_ao);
        cudaGetSymbolAddress((void**)&p_h,    g_h);
        cudaGetSymbolAddress((void**)&p_f1,   g_f1);
        cudaGetSymbolAddress((void**)&p_f2,   g_f2);
        cudaFuncSetAttribute(relw_mma, cudaFuncAttributeMaxDynamicSharedMemorySize, RELW_SMEM);
        cudaFuncSetAttribute(gemm_tf32<true, 0>, cudaFuncAttributeMaxDynamicSharedMemorySize, SM_BT);
        cudaFuncSetAttribute(gemm_tf32<false, 1>, cudaFuncAttributeMaxDynamicSharedMemorySize, SM_BN);
        cudaFuncSetAttribute(gemm_tf32<false, 2>, cudaFuncAttributeMaxDynamicSharedMemorySize, SM_BN);
    }

    dim3 blk(256);

    // 0a. prepass: relation -> bf16 (134MB)
    cvt_rel<<<ROWS_ * E_ / (8 * 256), 256>>>(relation);
    // 0b. prepass: interleaved bf16 weight tiles [h][k][128]
    build_bw<<<1024, 256>>>(rel_w);

    // 1. qkv = x @ in_w^T + in_b    (tf32)
    gemm_tf32<true, 0><<<dim3(1536/128, TB_/128), blk, SM_BT>>>(x, in_w, in_b, nullptr, p_qkv, TB_, 3*E_, E_);

    // 2. relation GEMM (bf16 HMMA, 128x128 tile, 2 CTAs/SM, 3-stage cp.async)
    relw_mma<<<dim3(H_, ROWS_/128), blk, RELW_SMEM>>>(rel_b);

    // 3. softmax + attn
    softmax_attn_kernel<<<TB_, 256>>>();

    // 4. out proj + residual       (tf32)
    gemm_tf32<false, 2><<<dim3(E_/128, TB_/128), blk, SM_BN>>>(p_attn, out_w, out_b, x, p_ao, TB_, E_, E_);

    // 5. LN1
    ln_kernel<<<TB_, 256>>>(p_ao, ln1_g, ln1_b, p_h);

    // 6. fc1 + relu                (tf32)
    gemm_tf32<false, 1><<<dim3(F_/128, TB_/128), blk, SM_BN>>>(p_h, fc1_w, fc1_b, nullptr, p_f1, TB_, F_, E_);

    // 7. fc2 + residual h          (tf32)
    gemm_tf32<false, 2><<<dim3(E_/128, TB_/128), blk, SM_BN>>>(p_f1, fc2_w, fc2_b, p_h, p_f2, TB_, E_, F_);

    // 8. LN2 -> out
    ln_kernel<<<TB_, 256>>>(p_f2, ln2_g, ln2_b, out);
}

// round 10
// speedup vs baseline: 3.6774x; 1.0519x over previous
#include <cuda_runtime.h>
#include <cuda_bf16.h>
#include <cstdint>

#define T_  64
#define B_  32
#define E_  512
#define H_  8
#define F_  2048
#define TB_ (T_*B_)        // 2048
#define ROWS_ (T_*T_*B_)   // 131072

// ---------------- scratch ----------------------------------------------------
__device__ float g_qkv[TB_ * 3 * E_];
__device__ float g_w[TB_ * H_ * T_];
__device__ float g_attn[TB_ * E_];
__device__ float g_ao[TB_ * E_];
__device__ float g_h[TB_ * E_];
__device__ float g_f1[TB_ * F_];
__device__ float g_f2[TB_ * E_];
__device__ __nv_bfloat16 g_arel[(size_t)ROWS_ * E_];   // relation in bf16 (134MB)
__device__ __nv_bfloat16 g_bw[H_ * E_ * 128];          // [h][k][2d interleaved ra/rb]

// ---------------- helpers ------------------------------------------------------
__device__ __forceinline__ uint32_t smem_u32(const void* p) {
    return (uint32_t)__cvta_generic_to_shared(p);
}
__device__ __forceinline__ void ldsm_x4(uint32_t& r0, uint32_t& r1, uint32_t& r2, uint32_t& r3, uint32_t a) {
    asm volatile("ldmatrix.sync.aligned.m8n8.x4.shared.b16 {%0,%1,%2,%3},[%4];"
                 : "=r"(r0), "=r"(r1), "=r"(r2), "=r"(r3) : "r"(a));
}
__device__ __forceinline__ void ldsm_x4_t(uint32_t& r0, uint32_t& r1, uint32_t& r2, uint32_t& r3, uint32_t a) {
    asm volatile("ldmatrix.sync.aligned.m8n8.x4.trans.shared.b16 {%0,%1,%2,%3},[%4];"
                 : "=r"(r0), "=r"(r1), "=r"(r2), "=r"(r3) : "r"(a));
}
__device__ __forceinline__ void mma16816(float* c, const uint32_t* a, const uint32_t* b) {
    asm volatile("mma.sync.aligned.m16n8k16.row.col.f32.bf16.bf16.f32 "
                 "{%0,%1,%2,%3},{%4,%5,%6,%7},{%8,%9},{%0,%1,%2,%3};"
                 : "+f"(c[0]), "+f"(c[1]), "+f"(c[2]), "+f"(c[3])
                 : "r"(a[0]), "r"(a[1]), "r"(a[2]), "r"(a[3]), "r"(b[0]), "r"(b[1]));
}
__device__ __forceinline__ void mma_tf32(float* c, const float* a, const float* b) {
    asm volatile("mma.sync.aligned.m16n8k8.row.col.f32.tf32.tf32.f32 "
                 "{%0,%1,%2,%3},{%4,%5,%6,%7},{%8,%9},{%0,%1,%2,%3};"
                 : "+f"(c[0]), "+f"(c[1]), "+f"(c[2]), "+f"(c[3])
                 : "r"(__float_as_uint(a[0])), "r"(__float_as_uint(a[1])),
                   "r"(__float_as_uint(a[2])), "r"(__float_as_uint(a[3])),
                   "r"(__float_as_uint(b[0])), "r"(__float_as_uint(b[1])));
}
__device__ __forceinline__ uint32_t f2bf2(float x, float y) {
    __nv_bfloat162 t = __floats2bfloat162_rn(x, y);
    return *reinterpret_cast<uint32_t*>(&t);
}
__device__ __forceinline__ float to_tf32(float x) {
    float y;
    asm("cvt.rna.tf32.f32 %0, %1;" : "=f"(y) : "f"(x));
    return y;
}
__device__ __forceinline__ float4 to_tf32_4(float4 v) {
    return make_float4(to_tf32(v.x), to_tf32(v.y), to_tf32(v.z), to_tf32(v.w));
}
#define CP_ASYNC16(saddr, gptr) \
    asm volatile("cp.async.cg.shared.global [%0], [%1], 16;" :: "r"(saddr), "l"(gptr) : "memory")
#define CP_COMMIT() asm volatile("cp.async.commit_group;" ::: "memory")
#define CP_WAIT1()  asm volatile("cp.async.wait_group 1;" ::: "memory")
#define CP_WAIT0()  asm volatile("cp.async.wait_group 0;" ::: "memory")

// ---------------- prepass: relation fp32 -> bf16 ------------------------------
__global__ __launch_bounds__(256) void cvt_rel(const float* __restrict__ rel)
{
    size_t i = ((size_t)blockIdx.x * 256 + threadIdx.x) * 8;
    float4 a = *(const float4*)(rel + i);
    float4 b = *(const float4*)(rel + i + 4);
    uint4 v = make_uint4(f2bf2(a.x, a.y), f2bf2(a.z, a.w),
                         f2bf2(b.x, b.y), f2bf2(b.z, b.w));
    *(uint4*)((char*)g_arel + i * 2) = v;
}

// ---------------- prepass: interleaved bf16 weight tiles [h][k][128] ----------
__global__ __launch_bounds__(256) void build_bw(const float* __restrict__ relw)
{
    int idx = blockIdx.x * 256 + threadIdx.x;    // 262144
    int d = idx & 63;
    int k = (idx >> 6) & 511;
    int h = idx >> 15;
    g_bw[((size_t)h*E_ + k) * 128 + 2*d    ] = __float2bfloat16(relw[(size_t)k*(2*E_) + h*64 + d]);
    g_bw[((size_t)h*E_ + k) * 128 + 2*d + 1] = __float2bfloat16(relw[(size_t)k*(2*E_) + E_ + h*64 + d]);
}

// ---------------- fused relation GEMM (bf16 HMMA, 3-stage, 2 CTAs/SM) ---------
// 128x128 tile (one head), 8 warps 4(m)x2(n), warp tile 32x64, acc=64 regs.
#define RSA_STRIDE 16384
#define RSB_BASE   49152
#define RSB_STRIDE 16384
#define RELW_SMEM  98304
__global__ void __launch_bounds__(256, 2) relw_mma(const float* __restrict__ relb)
{
    extern __shared__ char smem[];
    const uint32_t AsBase = smem_u32(smem);
    const uint32_t BsBase = AsBase + RSB_BASE;
    float* red = (float*)smem;

    const int h   = blockIdx.x;
    const int n0  = blockIdx.y * 128;
    const int tid = threadIdx.x;
    const int lane = tid & 31, warp = tid >> 5;
    const int warp_m = warp >> 1, warp_n = warp & 1;   // 4 x 2, warp tile 32x64

    float acc[2][8][4];
    #pragma unroll
    for (int i = 0; i < 2; i++)
        #pragma unroll
        for (int j = 0; j < 8; j++)
            #pragma unroll
            for (int k = 0; k < 4; k++) acc[i][j][k] = 0.f;

    const __nv_bfloat16* Ag = g_arel + (size_t)n0 * E_;
    const __nv_bfloat16* Bg = g_bw + (size_t)h * E_ * 128;

    auto load_stage = [&](int s, int buf) {
        uint32_t Ab = AsBase + buf * RSA_STRIDE;
        #pragma unroll
        for (int c = 0; c < 4; c++) {
            int idx = c * 256 + tid;
            int row = idx >> 3, cg = idx & 7;
            CP_ASYNC16(Ab + row*128 + (((cg ^ (row & 7)) << 4)),
                       Ag + (size_t)row * E_ + s*64 + cg*8);
        }
        uint32_t Bb = BsBase + buf * RSB_STRIDE;
        #pragma unroll
        for (int c = 0; c < 4; c++) {
            int idx = c * 256 + tid;
            int kr = idx >> 4, ng = idx & 15;
            CP_ASYNC16(Bb + kr*256 + (((ng ^ (kr & 7)) << 4)),
                       Bg + (size_t)(s*64 + kr) * 128 + ng*8);
        }
        CP_COMMIT();
    };

    load_stage(0, 0);
    load_stage(1, 1);

    const int a_r  = warp_m*32 + (lane & 15);
    const int a_kc = (lane >> 4) << 3;
    const int b_kr = lane & 15;
    const int b_nc = warp_n*64 + ((lane >> 4) << 3);

    #pragma unroll
    for (int s = 0; s < 8; s++) {
        if (s < 7) CP_WAIT1(); else CP_WAIT0();
        __syncthreads();
        if (s < 6) load_stage(s + 2, (s + 2) % 3);

        const uint32_t Ab = AsBase + (s % 3) * RSA_STRIDE;
        const uint32_t Bb = BsBase + (s % 3) * RSB_STRIDE;

        #pragma unroll
        for (int ks = 0; ks < 4; ks++) {
            uint32_t a[2][4];
            #pragma unroll
            for (int mi = 0; mi < 2; mi++) {
                int r  = a_r + mi*16;
                int kc = a_kc + ks*16;
                ldsm_x4(a[mi][0], a[mi][1], a[mi][2], a[mi][3],
                        Ab + r*128 + ((((kc >> 3) ^ (r & 7)) << 4)));
            }
            uint32_t b[8][2];
            #pragma unroll
            for (int g = 0; g < 4; g++) {
                int krow = b_kr + ks*16;
                int ncol = b_nc + g*16;
                ldsm_x4_t(b[2*g][0], b[2*g][1], b[2*g+1][0], b[2*g+1][1],
                          Bb + krow*256 + ((((ncol >> 3) ^ (krow & 7)) << 4)));
            }
            #pragma unroll
            for (int mi = 0; mi < 2; mi++)
                #pragma unroll
                for (int nf = 0; nf < 8; nf++)
                    mma16816(acc[mi][nf], a[mi], b[nf]);
        }
    }

    // ---- fused epilogue: (c0 + bra + q) * (c1 + brb + k), reduce over d --------
    const int tig = lane & 3, grp = lane >> 2;
    float part[2][2] = {{0.f, 0.f}, {0.f, 0.f}};
    #pragma unroll
    for (int nf = 0; nf < 8; nf++) {
        int d = warp_n*32 + nf*4 + tig;
        float bra = relb[h*64 + d];
        float brb = relb[E_ + h*64 + d];
        #pragma unroll
        for (int mi = 0; mi < 2; mi++)
            #pragma unroll
            for (int hf = 0; hf < 2; hf++) {
                int r  = warp_m*32 + mi*16 + grp + hf*8;
                int n  = n0 + r;
                int b  = n & 31;
                int ji = n >> 5;
                int ii = ji & 63, jj = ji >> 6;
                float q = g_qkv[(size_t)(ii*B_ + b) * (3*E_) + h*64 + d];
                float k = g_qkv[(size_t)(jj*B_ + b) * (3*E_) + E_ + h*64 + d];
                part[mi][hf] += (acc[mi][nf][hf*2+0] + bra + q) * (acc[mi][nf][hf*2+1] + brb + k);
            }
    }
    #pragma unroll
    for (int mi = 0; mi < 2; mi++)
        #pragma unroll
        for (int hf = 0; hf < 2; hf++) {
            float v = part[mi][hf];
            v += __shfl_xor_sync(~0u, v, 1);
            v += __shfl_xor_sync(~0u, v, 2);
            part[mi][hf] = v;
        }
    __syncthreads();
    if (tig == 0) {
        #pragma unroll
        for (int mi = 0; mi < 2; mi++)
            #pragma unroll
            for (int hf = 0; hf < 2; hf++) {
                int r = warp_m*32 + mi*16 + grp + hf*8;
                red[r*2 + warp_n] = part[mi][hf];
            }
    }
    __syncthreads();
    if (tid < 128) {
        int n  = n0 + tid;
        int b  = n & 31;
        int ji = n >> 5;
        int ii = ji & 63, jj = ji >> 6;
        g_w[((size_t)(ii*B_ + b) * H_ + h) * T_ + jj] =
            (red[tid*2] + red[tid*2 + 1]) * 0.015625f;
    }
}

// ---------------- tf32 GEMM: (64*MI)x128 tile, K-stage 32 ---------------------
// MI=2 -> 128-row tile (acc 64/thr), MI=1 -> 64-row tile (acc 32/thr, 2 CTAs/SM)
#define PA_ 36
#define PB_ 136
template<int MI, bool BTRANS, int EPI>
__global__ __launch_bounds__(256) void gemm_tf32(
    const float* __restrict__ A, const float* __restrict__ Bm,
    const float* __restrict__ bias, const float* __restrict__ add,
    float* __restrict__ C, int M, int N, int K)
{
    constexpr int MT = 64 * MI;
    extern __shared__ float sm[];
    const int AW = MT * PA_;
    const int BW = BTRANS ? 128 * PA_ : 32 * PB_;
    float* Asm[2] = { sm, sm + AW };
    float* Bsm[2] = { sm + 2*AW, sm + 2*AW + BW };

    const int tid = threadIdx.x;
    const int lane = tid & 31, warp = tid >> 5;
    const int wm = warp >> 1, wn = warp & 1;
    const int grp = lane >> 2, tig = lane & 3;
    const int m0 = blockIdx.y * MT;
    const int n0 = blockIdx.x * 128;

    float acc[MI][8][4];
    #pragma unroll
    for (int i = 0; i < MI; i++)
        #pragma unroll
        for (int j = 0; j < 8; j++)
            #pragma unroll
            for (int k = 0; k < 4; k++) acc[i][j][k] = 0.f;

    const int S = K >> 5;
    float4 pa[2*MI], pb[4];

    #pragma unroll
    for (int it = 0; it < 2*MI; it++) {
        int idx = it * 1024 + tid * 4;
        pa[it] = *(const float4*)(A + (size_t)(m0 + (idx >> 5)) * K + (idx & 31));
    }
    #pragma unroll
    for (int it = 0; it < 4; it++) {
        int idx = it * 1024 + tid * 4;
        if (BTRANS) pb[it] = *(const float4*)(Bm + (size_t)(n0 + (idx >> 5)) * K + (idx & 31));
        else        pb[it] = *(const float4*)(Bm + (size_t)(idx >> 7) * N + n0 + (idx & 127));
    }
    #pragma unroll
    for (int it = 0; it < 2*MI; it++) {
        int idx = it * 1024 + tid * 4;
        *(float4*)&Asm[0][(idx >> 5) * PA_ + (idx & 31)] = to_tf32_4(pa[it]);
    }
    #pragma unroll
    for (int it = 0; it < 4; it++) {
        int idx = it * 1024 + tid * 4;
        if (BTRANS) *(float4*)&Bsm[0][(idx >> 5) * PA_ + (idx & 31)] = to_tf32_4(pb[it]);
        else        *(float4*)&Bsm[0][(idx >> 7) * PB_ + (idx & 127)] = to_tf32_4(pb[it]);
    }
    __syncthreads();

    for (int s = 0; s < S; s++) {
        if (s < S - 1) {
            int k0 = (s + 1) * 32;
            #pragma unroll
            for (int it = 0; it < 2*MI; it++) {
                int idx = it * 1024 + tid * 4;
                pa[it] = *(const float4*)(A + (size_t)(m0 + (idx >> 5)) * K + k0 + (idx & 31));
            }
            #pragma unroll
            for (int it = 0; it < 4; it++) {
                int idx = it * 1024 + tid * 4;
                if (BTRANS) pb[it] = *(const float4*)(Bm + (size_t)(n0 + (idx >> 5)) * K + k0 + (idx & 31));
                else        pb[it] = *(const float4*)(Bm + (size_t)(k0 + (idx >> 7)) * N + n0 + (idx & 127));
            }
        }
        const float* Ab = Asm[s & 1];
        const float* Bb = Bsm[s & 1];
        #pragma unroll
        for (int ks = 0; ks < 4; ks++) {
            float a[MI][4];
            #pragma unroll
            for (int mi = 0; mi < MI; mi++) {
                int r = wm*(16*MI) + mi*16 + grp;
                int c = ks*8 + tig;
                a[mi][0] = Ab[r * PA_ + c];
                a[mi][1] = Ab[(r + 8) * PA_ + c];
                a[mi][2] = Ab[r * PA_ + c + 4];
                a[mi][3] = Ab[(r + 8) * PA_ + c + 4];
            }
            float b[8][2];
            #pragma unroll
            for (int nf = 0; nf < 8; nf++) {
                int n = wn*64 + nf*8 + grp;
                if (BTRANS) {
                    b[nf][0] = Bb[n * PA_ + ks*8 + tig];
                    b[nf][1] = Bb[n * PA_ + ks*8 + tig + 4];
                } else {
                    b[nf][0] = Bb[(ks*8 + tig) * PB_ + n];
                    b[nf][1] = Bb[(ks*8 + tig + 4) * PB_ + n];
                }
            }
            #pragma unroll
            for (int mi = 0; mi < MI; mi++)
                #pragma unroll
                for (int nf = 0; nf < 8; nf++)
                    mma_tf32(acc[mi][nf], a[mi], b[nf]);
        }
        if (s < S - 1) {
            __syncthreads();
            float* Ac = Asm[(s + 1) & 1];
            float* Bc = Bsm[(s + 1) & 1];
            #pragma unroll
            for (int it = 0; it < 2*MI; it++) {
                int idx = it * 1024 + tid * 4;
                *(float4*)&Ac[(idx >> 5) * PA_ + (idx & 31)] = to_tf32_4(pa[it]);
            }
            #pragma unroll
            for (int it = 0; it < 4; it++) {
                int idx = it * 1024 + tid * 4;
                if (BTRANS) *(float4*)&Bc[(idx >> 5) * PA_ + (idx & 31)] = to_tf32_4(pb[it]);
                else        *(float4*)&Bc[(idx >> 7) * PB_ + (idx & 127)] = to_tf32_4(pb[it]);
            }
            __syncthreads();
        }
    }

    #pragma unroll
    for (int mi = 0; mi < MI; mi++)
        #pragma unroll
        for (int hf = 0; hf < 2; hf++) {
            int row = m0 + wm*(16*MI) + mi*16 + grp + hf*8;
            #pragma unroll
            for (int nf = 0; nf < 8; nf++) {
                int col = n0 + wn*64 + nf*8 + tig*2;
                float v0 = acc[mi][nf][hf*2 + 0] + bias[col];
                float v1 = acc[mi][nf][hf*2 + 1] + bias[col + 1];
                if (EPI == 1) { v0 = fmaxf(v0, 0.f); v1 = fmaxf(v1, 0.f); }
                if (EPI == 2) {
                    v0 += add[(size_t)row * N + col];
                    v1 += add[(size_t)row * N + col + 1];
                }
                *(float2*)(C + (size_t)row * N + col) = make_float2(v0, v1);
            }
        }
}

// ---------------- softmax + attn, one CTA per (b, h): v staged once -----------
__global__ __launch_bounds__(256) void softmax_attn_kernel()
{
    const int b = blockIdx.x, h = blockIdx.y;
    __shared__ float p[64][68];
    __shared__ float vs[64][68];
    const int t = threadIdx.x;
    const int i = t >> 2, q = t & 3;
    const int d0 = q * 16;

    // stage v[j][d] (j = i role reused)
    {
        const float* src = g_qkv + (size_t)(i*B_ + b)*(3*E_) + 2*E_ + h*64 + d0;
        #pragma unroll
        for (int e = 0; e < 16; e += 4)
            *(float4*)&vs[i][d0 + e] = *(const float4*)(src + e);
    }

    // softmax over j for row i (4 threads per row, 16 j each)
    {
        float w[16];
        const float* wr = g_w + ((size_t)(i*B_ + b)*H_ + h)*T_ + d0;
        #pragma unroll
        for (int e = 0; e < 16; e += 4) {
            float4 v4 = *(const float4*)(wr + e);
            w[e] = v4.x; w[e+1] = v4.y; w[e+2] = v4.z; w[e+3] = v4.w;
        }
        float mx = w[0];
        #pragma unroll
        for (int e = 1; e < 16; e++) mx = fmaxf(mx, w[e]);
        mx = fmaxf(mx, __shfl_xor_sync(~0u, mx, 1));
        mx = fmaxf(mx, __shfl_xor_sync(~0u, mx, 2));
        float s = 0.f;
        #pragma unroll
        for (int e = 0; e < 16; e++) { w[e] = expf(w[e] - mx); s += w[e]; }
        s += __shfl_xor_sync(~0u, s, 1);
        s += __shfl_xor_sync(~0u, s, 2);
        float inv = 1.f / s;
        #pragma unroll
        for (int e = 0; e < 16; e++) p[i][d0 + e] = w[e] * inv;
    }
    __syncthreads();

    // attn[i][d0..d0+15] = sum_j p[i][j] * v[j][d]
    float acc[16] = {};
    for (int j = 0; j < 64; j++) {
        float pij = p[i][j];
        #pragma unroll
        for (int e = 0; e < 16; e += 4) {
            float4 v4 = *(float4*)&vs[j][d0 + e];
            acc[e]   = fmaf(pij, v4.x, acc[e]);
            acc[e+1] = fmaf(pij, v4.y, acc[e+1]);
            acc[e+2] = fmaf(pij, v4.z, acc[e+2]);
            acc[e+3] = fmaf(pij, v4.w, acc[e+3]);
        }
    }
    float* dst = g_attn + (size_t)(i*B_ + b)*E_ + h*64 + d0;
    #pragma unroll
    for (int e = 0; e < 16; e += 4)
        *(float4*)(dst + e) = make_float4(acc[e], acc[e+1], acc[e+2], acc[e+3]);
}

// ---------------- layernorm ----------------------------------------------------
__global__ __launch_bounds__(256) void ln_kernel(
    const float* __restrict__ in, const float* __restrict__ g,
    const float* __restrict__ b, float* __restrict__ out)
{
    int row = blockIdx.x;
    const float* r = in + (size_t)row * E_;
    int t = threadIdx.x;
    float v0 = r[t], v1 = r[t + 256];
    float s = v0 + v1, sq = v0*v0 + v1*v1;
    #pragma unroll
    for (int o = 16; o; o >>= 1) {
        s  += __shfl_xor_sync(~0u, s,  o);
        sq += __shfl_xor_sync(~0u, sq, o);
    }
    __shared__ float ss[8], ssq[8];
    int w = t >> 5, l = t & 31;
    if (l == 0) { ss[w] = s; ssq[w] = sq; }
    __syncthreads();
    if (w == 0) {
        s  = (l < 8) ? ss[l]  : 0.f;
        sq = (l < 8) ? ssq[l] : 0.f;
        #pragma unroll
        for (int o = 4; o; o >>= 1) {
            s  += __shfl_xor_sync(~0u, s,  o);
            sq += __shfl_xor_sync(~0u, sq, o);
        }
        if (l == 0) { ss[0] = s; ssq[0] = sq; }
    }
    __syncthreads();
    float mu   = ss[0]  * (1.f / E_);
    float var  = ssq[0] * (1.f / E_) - mu * mu;
    float rstd = rsqrtf(var + 1e-5f);
    out[(size_t)row*E_ + t]       = (v0 - mu) * rstd * g[t]       + b[t];
    out[(size_t)row*E_ + t + 256] = (v1 - mu) * rstd * g[t + 256] + b[t + 256];
}

// ---------------- launch --------------------------------------------------------
extern "C" void kernel_launch(void* const* d_in, const int* in_sizes, int n_in,
                              void* d_out, int out_size)
{
    const float* x        = (const float*)d_in[0];
    const float* relation = (const float*)d_in[1];
    const float* in_w     = (const float*)d_in[2];
    const float* in_b     = (const float*)d_in[3];
    const float* rel_w    = (const float*)d_in[4];
    const float* rel_b    = (const float*)d_in[5];
    const float* out_w    = (const float*)d_in[6];
    const float* out_b    = (const float*)d_in[7];
    const float* fc1_w    = (const float*)d_in[8];
    const float* fc1_b    = (const float*)d_in[9];
    const float* fc2_w    = (const float*)d_in[10];
    const float* fc2_b    = (const float*)d_in[11];
    const float* ln1_g    = (const float*)d_in[12];
    const float* ln1_b    = (const float*)d_in[13];
    const float* ln2_g    = (const float*)d_in[14];
    const float* ln2_b    = (const float*)d_in[15];
    float* out = (float*)d_out;

    const int SM_BT64  = (2*64*PA_  + 2*128*PA_) * 4;   // qkv, MI=1 BTRANS
    const int SM_BN64  = (2*64*PA_  + 2*32*PB_) * 4;    // out-proj/fc2, MI=1
    const int SM_BN128 = (2*128*PA_ + 2*32*PB_) * 4;    // fc1, MI=2

    static float *p_qkv = nullptr, *p_attn, *p_ao, *p_h, *p_f1, *p_f2;
    if (!p_qkv) {
        cudaGetSymbolAddress((void**)&p_qkv,  g_qkv);
        cudaGetSymbolAddress((void**)&p_attn, g_attn);
        cudaGetSymbolAddress((void**)&p_ao,   g_ao);
        cudaGetSymbolAddress((void**)&p_h,    g_h);
        cudaGetSymbolAddress((void**)&p_f1,   g_f1);
        cudaGetSymbolAddress((void**)&p_f2,   g_f2);
        cudaFuncSetAttribute(relw_mma, cudaFuncAttributeMaxDynamicSharedMemorySize, RELW_SMEM);
        cudaFuncSetAttribute(gemm_tf32<1, true, 0>,  cudaFuncAttributeMaxDynamicSharedMemorySize, SM_BT64);
        cudaFuncSetAttribute(gemm_tf32<1, false, 2>, cudaFuncAttributeMaxDynamicSharedMemorySize, SM_BN64);
        cudaFuncSetAttribute(gemm_tf32<2, false, 1>, cudaFuncAttributeMaxDynamicSharedMemorySize, SM_BN128);
    }

    dim3 blk(256);

    // 0a. prepass: relation -> bf16 (134MB)
    cvt_rel<<<ROWS_ * E_ / (8 * 256), 256>>>(relation);
    // 0b. prepass: interleaved bf16 weight tiles [h][k][128]
    build_bw<<<1024, 256>>>(rel_w);

    // 1. qkv = x @ in_w^T + in_b    (tf32, 64-row tiles: grid 384)
    gemm_tf32<1, true, 0><<<dim3(1536/128, TB_/64), blk, SM_BT64>>>(x, in_w, in_b, nullptr, p_qkv, TB_, 3*E_, E_);

    // 2. relation GEMM (bf16 HMMA, 128x128 tile, 2 CTAs/SM, 3-stage cp.async)
    relw_mma<<<dim3(H_, ROWS_/128), blk, RELW_SMEM>>>(rel_b);

    // 3. softmax + attn, CTA per (b,h)
    softmax_attn_kernel<<<dim3(B_, H_), 256>>>();

    // 4. out proj + residual       (tf32, 64-row tiles: grid 128)
    gemm_tf32<1, false, 2><<<dim3(E_/128, TB_/64), blk, SM_BN64>>>(p_attn, out_w, out_b, x, p_ao, TB_, E_, E_);

    // 5. LN1
    ln_kernel<<<TB_, 256>>>(p_ao, ln1_g, ln1_b, p_h);

    // 6. fc1 + relu                (tf32, 128-row tiles: grid 256)
    gemm_tf32<2, false, 1><<<dim3(F_/128, TB_/128), blk, SM_BN128>>>(p_h, fc1_w, fc1_b, nullptr, p_f1, TB_, F_, E_);

    // 7. fc2 + residual h          (tf32, 64-row tiles: grid 128)
    gemm_tf32<1, false, 2><<<dim3(E_/128, TB_/64), blk, SM_BN64>>>(p_f1, fc2_w, fc2_b, p_h, p_f2, TB_, E_, F_);

    // 8. LN2 -> out
    ln_kernel<<<TB_, 256>>>(p_f2, ln2_g, ln2_b, out);
}

// round 11
// speedup vs baseline: 4.1500x; 1.1285x over previous
#include <cuda_runtime.h>
#include <cuda_bf16.h>
#include <cstdint>

#define T_  64
#define B_  32
#define E_  512
#define H_  8
#define F_  2048
#define TB_ (T_*B_)        // 2048
#define ROWS_ (T_*T_*B_)   // 131072

// ---------------- scratch ----------------------------------------------------
__device__ float g_qkv[TB_ * 3 * E_];
__device__ float g_w[TB_ * H_ * T_];
__device__ float g_attn[TB_ * E_];
__device__ float g_ao[TB_ * E_];
__device__ float g_h[TB_ * E_];
__device__ float g_f1[TB_ * F_];
__device__ float g_f2[TB_ * E_];
__device__ __nv_bfloat16 g_arel[(size_t)ROWS_ * E_];   // relation in bf16 (134MB)
__device__ __nv_bfloat16 g_bw[H_ * E_ * 128];          // [h][k][2d interleaved ra/rb]

// ---------------- helpers ------------------------------------------------------
__device__ __forceinline__ uint32_t smem_u32(const void* p) {
    return (uint32_t)__cvta_generic_to_shared(p);
}
__device__ __forceinline__ void ldsm_x4(uint32_t& r0, uint32_t& r1, uint32_t& r2, uint32_t& r3, uint32_t a) {
    asm volatile("ldmatrix.sync.aligned.m8n8.x4.shared.b16 {%0,%1,%2,%3},[%4];"
                 : "=r"(r0), "=r"(r1), "=r"(r2), "=r"(r3) : "r"(a));
}
__device__ __forceinline__ void ldsm_x4_t(uint32_t& r0, uint32_t& r1, uint32_t& r2, uint32_t& r3, uint32_t a) {
    asm volatile("ldmatrix.sync.aligned.m8n8.x4.trans.shared.b16 {%0,%1,%2,%3},[%4];"
                 : "=r"(r0), "=r"(r1), "=r"(r2), "=r"(r3) : "r"(a));
}
__device__ __forceinline__ void mma16816(float* c, const uint32_t* a, const uint32_t* b) {
    asm volatile("mma.sync.aligned.m16n8k16.row.col.f32.bf16.bf16.f32 "
                 "{%0,%1,%2,%3},{%4,%5,%6,%7},{%8,%9},{%0,%1,%2,%3};"
                 : "+f"(c[0]), "+f"(c[1]), "+f"(c[2]), "+f"(c[3])
                 : "r"(a[0]), "r"(a[1]), "r"(a[2]), "r"(a[3]), "r"(b[0]), "r"(b[1]));
}
__device__ __forceinline__ void mma_tf32(float* c, const float* a, const float* b) {
    asm volatile("mma.sync.aligned.m16n8k8.row.col.f32.tf32.tf32.f32 "
                 "{%0,%1,%2,%3},{%4,%5,%6,%7},{%8,%9},{%0,%1,%2,%3};"
                 : "+f"(c[0]), "+f"(c[1]), "+f"(c[2]), "+f"(c[3])
                 : "r"(__float_as_uint(a[0])), "r"(__float_as_uint(a[1])),
                   "r"(__float_as_uint(a[2])), "r"(__float_as_uint(a[3])),
                   "r"(__float_as_uint(b[0])), "r"(__float_as_uint(b[1])));
}
__device__ __forceinline__ uint32_t f2bf2(float x, float y) {
    __nv_bfloat162 t = __floats2bfloat162_rn(x, y);
    return *reinterpret_cast<uint32_t*>(&t);
}
#define CP_ASYNC16(saddr, gptr) \
    asm volatile("cp.async.cg.shared.global [%0], [%1], 16;" :: "r"(saddr), "l"(gptr) : "memory")
#define CP_COMMIT() asm volatile("cp.async.commit_group;" ::: "memory")
#define CP_WAIT1()  asm volatile("cp.async.wait_group 1;" ::: "memory")
#define CP_WAIT0()  asm volatile("cp.async.wait_group 0;" ::: "memory")

// ---------------- prepass: relation fp32 -> bf16 ------------------------------
__global__ __launch_bounds__(256) void cvt_rel(const float* __restrict__ rel)
{
    size_t i = ((size_t)blockIdx.x * 256 + threadIdx.x) * 8;
    float4 a = *(const float4*)(rel + i);
    float4 b = *(const float4*)(rel + i + 4);
    uint4 v = make_uint4(f2bf2(a.x, a.y), f2bf2(a.z, a.w),
                         f2bf2(b.x, b.y), f2bf2(b.z, b.w));
    *(uint4*)((char*)g_arel + i * 2) = v;
}

// ---------------- prepass: interleaved bf16 weight tiles [h][k][128] ----------
__global__ __launch_bounds__(256) void build_bw(const float* __restrict__ relw)
{
    int idx = blockIdx.x * 256 + threadIdx.x;    // 262144
    int d = idx & 63;
    int k = (idx >> 6) & 511;
    int h = idx >> 15;
    g_bw[((size_t)h*E_ + k) * 128 + 2*d    ] = __float2bfloat16(relw[(size_t)k*(2*E_) + h*64 + d]);
    g_bw[((size_t)h*E_ + k) * 128 + 2*d + 1] = __float2bfloat16(relw[(size_t)k*(2*E_) + E_ + h*64 + d]);
}

// ---------------- fused relation GEMM (bf16 HMMA, 3-stage, 2 CTAs/SM) ---------
#define RSA_STRIDE 16384
#define RSB_BASE   49152
#define RSB_STRIDE 16384
#define RELW_SMEM  98304
__global__ void __launch_bounds__(256, 2) relw_mma(const float* __restrict__ relb)
{
    extern __shared__ char smem[];
    const uint32_t AsBase = smem_u32(smem);
    const uint32_t BsBase = AsBase + RSB_BASE;
    float* red = (float*)smem;

    const int h   = blockIdx.x;
    const int n0  = blockIdx.y * 128;
    const int tid = threadIdx.x;
    const int lane = tid & 31, warp = tid >> 5;
    const int warp_m = warp >> 1, warp_n = warp & 1;

    float acc[2][8][4];
    #pragma unroll
    for (int i = 0; i < 2; i++)
        #pragma unroll
        for (int j = 0; j < 8; j++)
            #pragma unroll
            for (int k = 0; k < 4; k++) acc[i][j][k] = 0.f;

    const __nv_bfloat16* Ag = g_arel + (size_t)n0 * E_;
    const __nv_bfloat16* Bg = g_bw + (size_t)h * E_ * 128;

    auto load_stage = [&](int s, int buf) {
        uint32_t Ab = AsBase + buf * RSA_STRIDE;
        #pragma unroll
        for (int c = 0; c < 4; c++) {
            int idx = c * 256 + tid;
            int row = idx >> 3, cg = idx & 7;
            CP_ASYNC16(Ab + row*128 + (((cg ^ (row & 7)) << 4)),
                       Ag + (size_t)row * E_ + s*64 + cg*8);
        }
        uint32_t Bb = BsBase + buf * RSB_STRIDE;
        #pragma unroll
        for (int c = 0; c < 4; c++) {
            int idx = c * 256 + tid;
            int kr = idx >> 4, ng = idx & 15;
            CP_ASYNC16(Bb + kr*256 + (((ng ^ (kr & 7)) << 4)),
                       Bg + (size_t)(s*64 + kr) * 128 + ng*8);
        }
        CP_COMMIT();
    };

    load_stage(0, 0);
    load_stage(1, 1);

    const int a_r  = warp_m*32 + (lane & 15);
    const int a_kc = (lane >> 4) << 3;
    const int b_kr = lane & 15;
    const int b_nc = warp_n*64 + ((lane >> 4) << 3);

    #pragma unroll
    for (int s = 0; s < 8; s++) {
        if (s < 7) CP_WAIT1(); else CP_WAIT0();
        __syncthreads();
        if (s < 6) load_stage(s + 2, (s + 2) % 3);

        const uint32_t Ab = AsBase + (s % 3) * RSA_STRIDE;
        const uint32_t Bb = BsBase + (s % 3) * RSB_STRIDE;

        #pragma unroll
        for (int ks = 0; ks < 4; ks++) {
            uint32_t a[2][4];
            #pragma unroll
            for (int mi = 0; mi < 2; mi++) {
                int r  = a_r + mi*16;
                int kc = a_kc + ks*16;
                ldsm_x4(a[mi][0], a[mi][1], a[mi][2], a[mi][3],
                        Ab + r*128 + ((((kc >> 3) ^ (r & 7)) << 4)));
            }
            uint32_t b[8][2];
            #pragma unroll
            for (int g = 0; g < 4; g++) {
                int krow = b_kr + ks*16;
                int ncol = b_nc + g*16;
                ldsm_x4_t(b[2*g][0], b[2*g][1], b[2*g+1][0], b[2*g+1][1],
                          Bb + krow*256 + ((((ncol >> 3) ^ (krow & 7)) << 4)));
            }
            #pragma unroll
            for (int mi = 0; mi < 2; mi++)
                #pragma unroll
                for (int nf = 0; nf < 8; nf++)
                    mma16816(acc[mi][nf], a[mi], b[nf]);
        }
    }

    // ---- fused epilogue --------------------------------------------------------
    const int tig = lane & 3, grp = lane >> 2;
    float part[2][2] = {{0.f, 0.f}, {0.f, 0.f}};
    #pragma unroll
    for (int nf = 0; nf < 8; nf++) {
        int d = warp_n*32 + nf*4 + tig;
        float bra = relb[h*64 + d];
        float brb = relb[E_ + h*64 + d];
        #pragma unroll
        for (int mi = 0; mi < 2; mi++)
            #pragma unroll
            for (int hf = 0; hf < 2; hf++) {
                int r  = warp_m*32 + mi*16 + grp + hf*8;
                int n  = n0 + r;
                int b  = n & 31;
                int ji = n >> 5;
                int ii = ji & 63, jj = ji >> 6;
                float q = g_qkv[(size_t)(ii*B_ + b) * (3*E_) + h*64 + d];
                float k = g_qkv[(size_t)(jj*B_ + b) * (3*E_) + E_ + h*64 + d];
                part[mi][hf] += (acc[mi][nf][hf*2+0] + bra + q) * (acc[mi][nf][hf*2+1] + brb + k);
            }
    }
    #pragma unroll
    for (int mi = 0; mi < 2; mi++)
        #pragma unroll
        for (int hf = 0; hf < 2; hf++) {
            float v = part[mi][hf];
            v += __shfl_xor_sync(~0u, v, 1);
            v += __shfl_xor_sync(~0u, v, 2);
            part[mi][hf] = v;
        }
    __syncthreads();
    if (tig == 0) {
        #pragma unroll
        for (int mi = 0; mi < 2; mi++)
            #pragma unroll
            for (int hf = 0; hf < 2; hf++) {
                int r = warp_m*32 + mi*16 + grp + hf*8;
                red[r*2 + warp_n] = part[mi][hf];
            }
    }
    __syncthreads();
    if (tid < 128) {
        int n  = n0 + tid;
        int b  = n & 31;
        int ji = n >> 5;
        int ii = ji & 63, jj = ji >> 6;
        g_w[((size_t)(ii*B_ + b) * H_ + h) * T_ + jj] =
            (red[tid*2] + red[tid*2 + 1]) * 0.015625f;
    }
}

// ---------------- tf32 GEMM, cp.async 3-stage, 2 CTAs/SM ----------------------
// (64*MI)x128 tile, K-stage 32. Raw fp32 fed to HMMA.tf32 (HW truncates to tf32).
#define GPA 36
#define GPB 136
template<int MI, bool BTRANS, int EPI>
__global__ __launch_bounds__(256, 2) void gemm_tf32(
    const float* __restrict__ A, const float* __restrict__ Bm,
    const float* __restrict__ bias, const float* __restrict__ add,
    float* __restrict__ C, int M, int N, int K)
{
    constexpr int MT = 64 * MI;
    constexpr int AW = MT * GPA;                       // words per A buf
    constexpr int BW = BTRANS ? 128 * GPA : 32 * GPB;  // words per B buf
    extern __shared__ float sm[];
    const uint32_t smemb = smem_u32(sm);
    const uint32_t AsU = smemb;
    const uint32_t BsU = smemb + 3 * AW * 4;

    const int tid = threadIdx.x;
    const int lane = tid & 31, warp = tid >> 5;
    const int wm = warp >> 1, wn = warp & 1;
    const int grp = lane >> 2, tig = lane & 3;
    const int m0 = blockIdx.y * MT;
    const int n0 = blockIdx.x * 128;

    float acc[MI][8][4];
    #pragma unroll
    for (int i = 0; i < MI; i++)
        #pragma unroll
        for (int j = 0; j < 8; j++)
            #pragma unroll
            for (int k = 0; k < 4; k++) acc[i][j][k] = 0.f;

    const int S = K >> 5;

    auto load_stage = [&](int s, int buf) {
        uint32_t Ab = AsU + buf * AW * 4;
        #pragma unroll
        for (int c = 0; c < 2*MI; c++) {
            int idx = c * 256 + tid;                 // MT*8 chunks of 16B
            int row = idx >> 3, cg = idx & 7;
            CP_ASYNC16(Ab + row*(GPA*4) + cg*16,
                       A + (size_t)(m0 + row) * K + s*32 + cg*4);
        }
        uint32_t Bb = BsU + buf * BW * 4;
        #pragma unroll
        for (int c = 0; c < 4; c++) {
            int idx = c * 256 + tid;                 // 1024 chunks of 16B
            if (BTRANS) {
                int nr = idx >> 3, cg = idx & 7;
                CP_ASYNC16(Bb + nr*(GPA*4) + cg*16,
                           Bm + (size_t)(n0 + nr) * K + s*32 + cg*4);
            } else {
                int kr = idx >> 5, ng = idx & 31;
                CP_ASYNC16(Bb + kr*(GPB*4) + ng*16,
                           Bm + (size_t)(s*32 + kr) * N + n0 + ng*4);
            }
        }
        CP_COMMIT();
    };

    load_stage(0, 0);
    load_stage(1, 1);

    for (int s = 0; s < S; s++) {
        if (s < S - 1) CP_WAIT1(); else CP_WAIT0();
        __syncthreads();
        if (s < S - 2) load_stage(s + 2, (s + 2) % 3);

        const float* Ab = sm + (s % 3) * AW;
        const float* Bb = sm + 3 * AW + (s % 3) * BW;
        #pragma unroll
        for (int ks = 0; ks < 4; ks++) {
            float a[MI][4];
            #pragma unroll
            for (int mi = 0; mi < MI; mi++) {
                int r = wm*(16*MI) + mi*16 + grp;
                int c = ks*8 + tig;
                a[mi][0] = Ab[r * GPA + c];
                a[mi][1] = Ab[(r + 8) * GPA + c];
                a[mi][2] = Ab[r * GPA + c + 4];
                a[mi][3] = Ab[(r + 8) * GPA + c + 4];
            }
            float b[8][2];
            #pragma unroll
            for (int nf = 0; nf < 8; nf++) {
                int n = wn*64 + nf*8 + grp;
                if (BTRANS) {
                    b[nf][0] = Bb[n * GPA + ks*8 + tig];
                    b[nf][1] = Bb[n * GPA + ks*8 + tig + 4];
                } else {
                    b[nf][0] = Bb[(ks*8 + tig) * GPB + n];
                    b[nf][1] = Bb[(ks*8 + tig + 4) * GPB + n];
                }
            }
            #pragma unroll
            for (int mi = 0; mi < MI; mi++)
                #pragma unroll
                for (int nf = 0; nf < 8; nf++)
                    mma_tf32(acc[mi][nf], a[mi], b[nf]);
        }
    }

    #pragma unroll
    for (int mi = 0; mi < MI; mi++)
        #pragma unroll
        for (int hf = 0; hf < 2; hf++) {
            int row = m0 + wm*(16*MI) + mi*16 + grp + hf*8;
            #pragma unroll
            for (int nf = 0; nf < 8; nf++) {
                int col = n0 + wn*64 + nf*8 + tig*2;
                float v0 = acc[mi][nf][hf*2 + 0] + bias[col];
                float v1 = acc[mi][nf][hf*2 + 1] + bias[col + 1];
                if (EPI == 1) { v0 = fmaxf(v0, 0.f); v1 = fmaxf(v1, 0.f); }
                if (EPI == 2) {
                    v0 += add[(size_t)row * N + col];
                    v1 += add[(size_t)row * N + col + 1];
                }
                *(float2*)(C + (size_t)row * N + col) = make_float2(v0, v1);
            }
        }
}

// ---------------- softmax + attn, one CTA per (b, h) --------------------------
__global__ __launch_bounds__(256) void softmax_attn_kernel()
{
    const int b = blockIdx.x, h = blockIdx.y;
    __shared__ float p[64][68];
    __shared__ float vs[64][68];
    const int t = threadIdx.x;
    const int i = t >> 2, q = t & 3;
    const int d0 = q * 16;

    {
        const float* src = g_qkv + (size_t)(i*B_ + b)*(3*E_) + 2*E_ + h*64 + d0;
        #pragma unroll
        for (int e = 0; e < 16; e += 4)
            *(float4*)&vs[i][d0 + e] = *(const float4*)(src + e);
    }
    {
        float w[16];
        const float* wr = g_w + ((size_t)(i*B_ + b)*H_ + h)*T_ + d0;
        #pragma unroll
        for (int e = 0; e < 16; e += 4) {
            float4 v4 = *(const float4*)(wr + e);
            w[e] = v4.x; w[e+1] = v4.y; w[e+2] = v4.z; w[e+3] = v4.w;
        }
        float mx = w[0];
        #pragma unroll
        for (int e = 1; e < 16; e++) mx = fmaxf(mx, w[e]);
        mx = fmaxf(mx, __shfl_xor_sync(~0u, mx, 1));
        mx = fmaxf(mx, __shfl_xor_sync(~0u, mx, 2));
        float s = 0.f;
        #pragma unroll
        for (int e = 0; e < 16; e++) { w[e] = expf(w[e] - mx); s += w[e]; }
        s += __shfl_xor_sync(~0u, s, 1);
        s += __shfl_xor_sync(~0u, s, 2);
        float inv = 1.f / s;
        #pragma unroll
        for (int e = 0; e < 16; e++) p[i][d0 + e] = w[e] * inv;
    }
    __syncthreads();

    float acc[16] = {};
    for (int j = 0; j < 64; j++) {
        float pij = p[i][j];
        #pragma unroll
        for (int e = 0; e < 16; e += 4) {
            float4 v4 = *(float4*)&vs[j][d0 + e];
            acc[e]   = fmaf(pij, v4.x, acc[e]);
            acc[e+1] = fmaf(pij, v4.y, acc[e+1]);
            acc[e+2] = fmaf(pij, v4.z, acc[e+2]);
            acc[e+3] = fmaf(pij, v4.w, acc[e+3]);
        }
    }
    float* dst = g_attn + (size_t)(i*B_ + b)*E_ + h*64 + d0;
    #pragma unroll
    for (int e = 0; e < 16; e += 4)
        *(float4*)(dst + e) = make_float4(acc[e], acc[e+1], acc[e+2], acc[e+3]);
}

// ---------------- layernorm ----------------------------------------------------
__global__ __launch_bounds__(256) void ln_kernel(
    const float* __restrict__ in, const float* __restrict__ g,
    const float* __restrict__ b, float* __restrict__ out)
{
    int row = blockIdx.x;
    const float* r = in + (size_t)row * E_;
    int t = threadIdx.x;
    float v0 = r[t], v1 = r[t + 256];
    float s = v0 + v1, sq = v0*v0 + v1*v1;
    #pragma unroll
    for (int o = 16; o; o >>= 1) {
        s  += __shfl_xor_sync(~0u, s,  o);
        sq += __shfl_xor_sync(~0u, sq, o);
    }
    __shared__ float ss[8], ssq[8];
    int w = t >> 5, l = t & 31;
    if (l == 0) { ss[w] = s; ssq[w] = sq; }
    __syncthreads();
    if (w == 0) {
        s  = (l < 8) ? ss[l]  : 0.f;
        sq = (l < 8) ? ssq[l] : 0.f;
        #pragma unroll
        for (int o = 4; o; o >>= 1) {
            s  += __shfl_xor_sync(~0u, s,  o);
            sq += __shfl_xor_sync(~0u, sq, o);
        }
        if (l == 0) { ss[0] = s; ssq[0] = sq; }
    }
    __syncthreads();
    float mu   = ss[0]  * (1.f / E_);
    float var  = ssq[0] * (1.f / E_) - mu * mu;
    float rstd = rsqrtf(var + 1e-5f);
    out[(size_t)row*E_ + t]       = (v0 - mu) * rstd * g[t]       + b[t];
    out[(size_t)row*E_ + t + 256] = (v1 - mu) * rstd * g[t + 256] + b[t + 256];
}

// ---------------- launch --------------------------------------------------------
extern "C" void kernel_launch(void* const* d_in, const int* in_sizes, int n_in,
                              void* d_out, int out_size)
{
    const float* x        = (const float*)d_in[0];
    const float* relation = (const float*)d_in[1];
    const float* in_w     = (const float*)d_in[2];
    const float* in_b     = (const float*)d_in[3];
    const float* rel_w    = (const float*)d_in[4];
    const float* rel_b    = (const float*)d_in[5];
    const float* out_w    = (const float*)d_in[6];
    const float* out_b    = (const float*)d_in[7];
    const float* fc1_w    = (const float*)d_in[8];
    const float* fc1_b    = (const float*)d_in[9];
    const float* fc2_w    = (const float*)d_in[10];
    const float* fc2_b    = (const float*)d_in[11];
    const float* ln1_g    = (const float*)d_in[12];
    const float* ln1_b    = (const float*)d_in[13];
    const float* ln2_g    = (const float*)d_in[14];
    const float* ln2_b    = (const float*)d_in[15];
    float* out = (float*)d_out;

    const int SM_BT64  = 3 * (64*GPA  + 128*GPA) * 4;   // 82944  (qkv)
    const int SM_BN64  = 3 * (64*GPA  + 32*GPB) * 4;    // 79872  (out/fc2)
    const int SM_BN128 = 3 * (128*GPA + 32*GPB) * 4;    // 107520 (fc1)

    static float *p_qkv = nullptr, *p_attn, *p_ao, *p_h, *p_f1, *p_f2;
    static cudaStream_t s_side;
    static cudaEvent_t ev_fork, ev_join;
    if (!p_qkv) {
        cudaGetSymbolAddress((void**)&p_qkv,  g_qkv);
        cudaGetSymbolAddress((void**)&p_attn, g_attn);
        cudaGetSymbolAddress((void**)&p_ao,   g_ao);
        cudaGetSymbolAddress((void**)&p_h,    g_h);
        cudaGetSymbolAddress((void**)&p_f1,   g_f1);
        cudaGetSymbolAddress((void**)&p_f2,   g_f2);
        cudaFuncSetAttribute(relw_mma, cudaFuncAttributeMaxDynamicSharedMemorySize, RELW_SMEM);
        cudaFuncSetAttribute(gemm_tf32<1, true, 0>,  cudaFuncAttributeMaxDynamicSharedMemorySize, SM_BT64);
        cudaFuncSetAttribute(gemm_tf32<1, false, 2>, cudaFuncAttributeMaxDynamicSharedMemorySize, SM_BN64);
        cudaFuncSetAttribute(gemm_tf32<2, false, 1>, cudaFuncAttributeMaxDynamicSharedMemorySize, SM_BN128);
        cudaStreamCreateWithFlags(&s_side, cudaStreamNonBlocking);
        cudaEventCreateWithFlags(&ev_fork, cudaEventDisableTiming);
        cudaEventCreateWithFlags(&ev_join, cudaEventDisableTiming);
    }

    dim3 blk(256);

    // ---- fork: cvt_rel on side stream, weights+qkv on main stream -------------
    cudaEventRecord(ev_fork, 0);
    cudaStreamWaitEvent(s_side, ev_fork, 0);
    cvt_rel<<<ROWS_ * E_ / (8 * 256), 256, 0, s_side>>>(relation);
    cudaEventRecord(ev_join, s_side);

    build_bw<<<1024, 256>>>(rel_w);
    gemm_tf32<1, true, 0><<<dim3(1536/128, TB_/64), blk, SM_BT64>>>(x, in_w, in_b, nullptr, p_qkv, TB_, 3*E_, E_);

    cudaStreamWaitEvent(0, ev_join, 0);   // join before relw reads g_arel

    // 2. relation GEMM (bf16 HMMA) + fused logits
    relw_mma<<<dim3(H_, ROWS_/128), blk, RELW_SMEM>>>(rel_b);

    // 3. softmax + attn, CTA per (b,h)
    softmax_attn_kernel<<<dim3(B_, H_), 256>>>();

    // 4. out proj + residual
    gemm_tf32<1, false, 2><<<dim3(E_/128, TB_/64), blk, SM_BN64>>>(p_attn, out_w, out_b, x, p_ao, TB_, E_, E_);

    // 5. LN1
    ln_kernel<<<TB_, 256>>>(p_ao, ln1_g, ln1_b, p_h);

    // 6. fc1 + relu
    gemm_tf32<2, false, 1><<<dim3(F_/128, TB_/128), blk, SM_BN128>>>(p_h, fc1_w, fc1_b, nullptr, p_f1, TB_, F_, E_);

    // 7. fc2 + residual h
    gemm_tf32<1, false, 2><<<dim3(E_/128, TB_/64), blk, SM_BN64>>>(p_f1, fc2_w, fc2_b, p_h, p_f2, TB_, E_, F_);

    // 8. LN2 -> out
    ln_kernel<<<TB_, 256>>>(p_f2, ln2_g, ln2_b, out);
}